// round 2
// baseline (speedup 1.0000x reference)
#include <cuda_runtime.h>
#include <cstdint>

// ===================== problem constants =====================
#define DIM    128      // D
#define HEADS  4        // H
#define DE     32       // edge feature dim
#define HD     512      // H*D
#define DHID   2048
#define DOUT   64
#define NMAX   16384
#define EMAX   131072
#define ETMAX  (EMAX + NMAX)
#define EPSN   1e-5f
#define SLOPE  0.2f

// ===================== scratch (static device globals; no allocs) ==========
__device__ float    g_xn0[NMAX * DIM];
__device__ float    g_xl[NMAX * HD];
__device__ float    g_xr[NMAX * HD];
__device__ float    g_eam[NMAX * DE];
__device__ float    g_deg[NMAX];
__device__ unsigned g_smax[NMAX * HEADS];
__device__ float    g_den[NMAX * HEADS];
__device__ float    g_sc[ETMAX * HEADS];
__device__ float    g_agg[NMAX * HD];
__device__ float    g_s1[NMAX * DIM];
__device__ float    g_s2[NMAX * DIM];
__device__ float    g_s3[NMAX * DIM];
__device__ float    g_s4[NMAX * DIM];
__device__ float    g_h1[NMAX * DHID];
__device__ float    g_oc[NMAX * DOUT];
__device__ double   g_stats[8];

// ===================== helpers =====================
__device__ __forceinline__ unsigned fenc(float f) {
    unsigned u = __float_as_uint(f);
    return u ^ ((u >> 31) ? 0xFFFFFFFFu : 0x80000000u);
}
__device__ __forceinline__ float fdec(unsigned u) {
    unsigned v = u ^ ((u >> 31) ? 0x80000000u : 0xFFFFFFFFu);
    return __uint_as_float(v);
}

// ===================== norm stats: sum & sumsq in fp64 =====================
__global__ void stats_kernel(const float* __restrict__ x, double* __restrict__ st, int n) {
    double s = 0.0, s2 = 0.0;
    for (int i = blockIdx.x * blockDim.x + threadIdx.x; i < n; i += gridDim.x * blockDim.x) {
        float v = x[i];
        s += (double)v;
        s2 += (double)v * (double)v;
    }
    __shared__ double sh[256], sh2[256];
    int tid = threadIdx.x;
    sh[tid] = s; sh2[tid] = s2;
    __syncthreads();
    for (int o = 128; o > 0; o >>= 1) {
        if (tid < o) { sh[tid] += sh[tid + o]; sh2[tid] += sh2[tid + o]; }
        __syncthreads();
    }
    if (tid == 0) {
        atomicAdd(&st[0], sh[0]);
        atomicAdd(&st[1], sh2[0]);
    }
}

__global__ void norm_apply_kernel(const float* __restrict__ x, float* __restrict__ y,
                                  const float* __restrict__ w, const float* __restrict__ b,
                                  const double* __restrict__ st, int n, int C) {
    int i = blockIdx.x * blockDim.x + threadIdx.x;
    if (i >= n) return;
    double cnt = (double)n;
    double mu_d = st[0] / cnt;
    double var_d = st[1] / cnt - mu_d * mu_d;
    if (var_d < 0.0) var_d = 0.0;
    float mu = (float)mu_d;
    float inv = 1.0f / ((float)sqrt(var_d) + EPSN);
    int c = i % C;
    y[i] = (x[i] - mu) * inv * w[c] + b[c];
}

// ===================== generic tiled SGEMM: C = A[M,K] * B[N,K]^T + bias ====
// optional relu, optional residual add (res[M,N])
template <bool RELU, bool RES>
__global__ void gemm_kernel(const float* __restrict__ A, const float* __restrict__ B,
                            const float* __restrict__ bias, const float* __restrict__ res,
                            float* __restrict__ C, int M, int N, int K) {
    constexpr int BM = 128, BN = 64, BK = 16, TM = 8, TN = 4, THREADS = 256;
    __shared__ float As[BK][BM];
    __shared__ float Bs[BK][BN];
    int tid = threadIdx.x;
    int bm = blockIdx.y * BM, bn = blockIdx.x * BN;
    int tcol = tid & 15;   // 0..15 (n dir, BN/TN=16)
    int trow = tid >> 4;   // 0..15 (m dir, BM/TM=16)
    float acc[TM][TN];
    #pragma unroll
    for (int i = 0; i < TM; i++)
        #pragma unroll
        for (int j = 0; j < TN; j++) acc[i][j] = 0.f;

    for (int k0 = 0; k0 < K; k0 += BK) {
        // load A tile (BM x BK), float4 along K, store transposed
        #pragma unroll
        for (int i = tid; i < BM * BK / 4; i += THREADS) {
            int r = i >> 2;            // /(BK/4)
            int c = (i & 3) << 2;
            float4 v = *(const float4*)(A + (size_t)(bm + r) * K + k0 + c);
            As[c + 0][r] = v.x; As[c + 1][r] = v.y; As[c + 2][r] = v.z; As[c + 3][r] = v.w;
        }
        // load B tile (BN x BK)
        #pragma unroll
        for (int i = tid; i < BN * BK / 4; i += THREADS) {
            int r = i >> 2;
            int c = (i & 3) << 2;
            float4 v = *(const float4*)(B + (size_t)(bn + r) * K + k0 + c);
            Bs[c + 0][r] = v.x; Bs[c + 1][r] = v.y; Bs[c + 2][r] = v.z; Bs[c + 3][r] = v.w;
        }
        __syncthreads();
        #pragma unroll
        for (int k = 0; k < BK; k++) {
            float4 a0 = *(const float4*)&As[k][trow * TM];
            float4 a1 = *(const float4*)&As[k][trow * TM + 4];
            float4 b0 = *(const float4*)&Bs[k][tcol * TN];
            float av[TM] = {a0.x, a0.y, a0.z, a0.w, a1.x, a1.y, a1.z, a1.w};
            float bv[TN] = {b0.x, b0.y, b0.z, b0.w};
            #pragma unroll
            for (int i = 0; i < TM; i++)
                #pragma unroll
                for (int j = 0; j < TN; j++) acc[i][j] += av[i] * bv[j];
        }
        __syncthreads();
    }
    int row0 = bm + trow * TM;
    int col0 = bn + tcol * TN;
    #pragma unroll
    for (int i = 0; i < TM; i++) {
        size_t base = (size_t)(row0 + i) * N + col0;
        #pragma unroll
        for (int j = 0; j < TN; j++) {
            float v = acc[i][j] + bias[col0 + j];
            if (RELU) v = v > 0.f ? v : 0.f;
            if (RES) v += res[base + j];
            C[base + j] = v;
        }
    }
}

// ===================== GAT edge kernels =====================
__global__ void degea_kernel(const int* __restrict__ edst, const float* __restrict__ ea,
                             float* __restrict__ eam, float* __restrict__ deg, int E) {
    int i = blockIdx.x * blockDim.x + threadIdx.x;
    if (i >= E * DE) return;
    int e = i >> 5, k = i & 31;
    int d = __ldg(edst + e);
    atomicAdd(&eam[d * DE + k], ea[i]);
    if (k == 0) atomicAdd(&deg[d], 1.f);
}

__global__ void eamdiv_kernel(float* __restrict__ eam, const float* __restrict__ deg, int n32) {
    int i = blockIdx.x * blockDim.x + threadIdx.x;
    if (i >= n32) return;
    eam[i] *= 1.f / fmaxf(deg[i >> 5], 1.f);
}

__global__ void init_smax_kernel(unsigned* __restrict__ smax, int n) {
    int i = blockIdx.x * blockDim.x + threadIdx.x;
    if (i < n) smax[i] = 0x007FFFFFu;  // fenc(-inf)
}

// per-edge fused:  z = lrelu(xl[src] + xr[dst] + ea@We^T); score = z . att  (per head)
#define EPB 16
#define SCORE_SMEM (512 * 36 * 4 + 512 * 4 + EPB * 32 * 4)
__global__ void score_kernel(const float* __restrict__ XL, const float* __restrict__ XR,
                             const int* __restrict__ esrc, const int* __restrict__ edst,
                             const float* __restrict__ eattr, const float* __restrict__ eam,
                             const float* __restrict__ We, const float* __restrict__ att,
                             float* __restrict__ SC, unsigned* __restrict__ SMAX,
                             int E, int ET) {
    extern __shared__ float sm[];
    float* We_s = sm;                    // 512 rows x (32 data + 4 pad) floats
    float* att_s = sm + 512 * 36;        // 512
    float* ea_s = att_s + 512;           // EPB * 32
    __shared__ int src_s[EPB], dst_s[EPB];
    __shared__ float sc_s[HEADS];
    int tid = threadIdx.x;
    const float4* We4 = (const float4*)We;
    float4* Ws4 = (float4*)We_s;
    for (int i = tid; i < 512 * 8; i += 256) {
        int r = i >> 3, k4 = i & 7;
        Ws4[r * 9 + k4] = We4[i];
    }
    for (int i = tid; i < 512; i += 256) att_s[i] = att[i];
    int e0 = blockIdx.x * EPB;
    for (int i = tid; i < EPB * 32; i += 256) {
        int el = i >> 5, k = i & 31;
        int e = e0 + el;
        float v = 0.f;
        if (e < ET) v = (e < E) ? eattr[(size_t)e * DE + k] : eam[(size_t)(e - E) * DE + k];
        ea_s[el * 32 + k] = v;
    }
    if (tid < EPB) {
        int e = e0 + tid;
        if (e < ET) {
            src_s[tid] = (e < E) ? esrc[e] : (e - E);
            dst_s[tid] = (e < E) ? edst[e] : (e - E);
        }
    }
    __syncthreads();
    int lane = tid & 31;
    int h0 = tid >> 7;  // warp-uniform
    for (int ee = 0; ee < EPB; ee++) {
        int e = e0 + ee;
        if (e >= ET) break;
        if (tid < HEADS) sc_s[tid] = 0.f;
        __syncthreads();
        int s = src_s[ee], d = dst_s[ee];
        const float4* ea4 = (const float4*)(ea_s + ee * 32);
        float c0v = 0.f, c1v = 0.f;
        #pragma unroll
        for (int p = 0; p < 2; p++) {
            int idx = tid + p * 256;
            float v = __ldg(XL + (size_t)s * HD + idx) + __ldg(XR + (size_t)d * HD + idx);
            float4 acc = make_float4(0.f, 0.f, 0.f, 0.f);
            #pragma unroll
            for (int k4 = 0; k4 < 8; k4++) {
                float4 w = Ws4[idx * 9 + k4];
                float4 a = ea4[k4];
                acc.x += w.x * a.x; acc.y += w.y * a.y;
                acc.z += w.z * a.z; acc.w += w.w * a.w;
            }
            v += acc.x + acc.y + acc.z + acc.w;
            v = v > 0.f ? v : SLOPE * v;
            float c = v * att_s[idx];
            if (p == 0) c0v = c; else c1v = c;
        }
        #pragma unroll
        for (int o = 16; o > 0; o >>= 1) {
            c0v += __shfl_down_sync(0xFFFFFFFFu, c0v, o);
            c1v += __shfl_down_sync(0xFFFFFFFFu, c1v, o);
        }
        if (lane == 0) {
            atomicAdd(&sc_s[h0], c0v);
            atomicAdd(&sc_s[h0 + 2], c1v);
        }
        __syncthreads();
        if (tid < HEADS) {
            float sv = sc_s[tid];
            SC[(size_t)e * HEADS + tid] = sv;
            atomicMax(&SMAX[(size_t)d * HEADS + tid], fenc(sv));
        }
    }
}

__global__ void exp_kernel(float* __restrict__ SC, const unsigned* __restrict__ SMAX,
                           float* __restrict__ den, const int* __restrict__ edst,
                           int E, int ET) {
    int i = blockIdx.x * blockDim.x + threadIdx.x;
    if (i >= ET * HEADS) return;
    int e = i >> 2, h = i & 3;
    int d = (e < E) ? __ldg(edst + e) : (e - E);
    float m = fdec(SMAX[d * HEADS + h]);
    float ex = expf(SC[i] - m);
    SC[i] = ex;
    atomicAdd(&den[d * HEADS + h], ex);
}

__global__ void alpha_kernel(float* __restrict__ SC, const float* __restrict__ den,
                             const int* __restrict__ edst, float* __restrict__ out_alpha,
                             int E, int ET, int write_out) {
    int i = blockIdx.x * blockDim.x + threadIdx.x;
    if (i >= ET * HEADS) return;
    int e = i >> 2, h = i & 3;
    int d = (e < E) ? __ldg(edst + e) : (e - E);
    float a = SC[i] / den[d * HEADS + h];
    SC[i] = a;
    if (write_out) out_alpha[i] = a;
}

// one warp per edge: AGG[dst] += XL[src] * alpha  (512 floats as 16 red.v4 per lane-group)
__global__ void aggregate_kernel(const float* __restrict__ XL, const float* __restrict__ SC,
                                 const int* __restrict__ esrc, const int* __restrict__ edst,
                                 float* __restrict__ AGG, int E, int ET) {
    int warp = (blockIdx.x * blockDim.x + threadIdx.x) >> 5;
    int lane = threadIdx.x & 31;
    if (warp >= ET) return;
    int e = warp;
    int s = (e < E) ? __ldg(esrc + e) : (e - E);
    int d = (e < E) ? __ldg(edst + e) : (e - E);
    float4 al = *(const float4*)(SC + (size_t)e * HEADS);
    float alph[4] = {al.x, al.y, al.z, al.w};
    const float4* xl4 = (const float4*)(XL + (size_t)s * HD);
    float* base = AGG + (size_t)d * HD;
    #pragma unroll
    for (int j = 0; j < 4; j++) {
        int i4 = lane + 32 * j;           // float4 index 0..127
        float a = alph[i4 >> 5];          // head, uniform within a float4
        float4 v = __ldg(xl4 + i4);
        float* p = base + i4 * 4;
        asm volatile("red.global.add.v4.f32 [%0], {%1,%2,%3,%4};"
                     :: "l"(p), "f"(v.x * a), "f"(v.y * a), "f"(v.z * a), "f"(v.w * a)
                     : "memory");
    }
}

__global__ void headmean_kernel(const float* __restrict__ xn0, const float* __restrict__ agg,
                                const float* __restrict__ gb, float* __restrict__ s1, int total) {
    int i = blockIdx.x * blockDim.x + threadIdx.x;
    if (i >= total) return;
    int c = i & 127;
    int n = i >> 7;
    const float* a = agg + (size_t)n * HD;
    s1[i] = xn0[i] + 0.25f * (a[c] + a[c + 128] + a[c + 256] + a[c + 384]) + gb[c];
}

// ===================== launch =====================
extern "C" void kernel_launch(void* const* d_in, const int* in_sizes, int n_in,
                              void* d_out, int out_size) {
    const float* x   = (const float*)d_in[0];
    const int* ei    = (const int*)d_in[1];
    const float* ea  = (const float*)d_in[2];
    // d_in[3] = batch (unused, all zeros)
    const float* Wl  = (const float*)d_in[4];
    const float* bl  = (const float*)d_in[5];
    const float* Wr  = (const float*)d_in[6];
    const float* br  = (const float*)d_in[7];
    const float* We  = (const float*)d_in[8];
    const float* att = (const float*)d_in[9];
    const float* gb  = (const float*)d_in[10];
    const float* W1  = (const float*)d_in[11];
    const float* b1  = (const float*)d_in[12];
    const float* W2  = (const float*)d_in[13];
    const float* b2  = (const float*)d_in[14];
    const float* Wc  = (const float*)d_in[15];
    const float* bc  = (const float*)d_in[16];
    const float* nw0 = (const float*)d_in[17];
    const float* nb0 = (const float*)d_in[18];
    const float* nw1 = (const float*)d_in[19];
    const float* nb1 = (const float*)d_in[20];
    const float* nw2 = (const float*)d_in[21];
    const float* nb2 = (const float*)d_in[22];
    const float* nw3 = (const float*)d_in[23];
    const float* nb3 = (const float*)d_in[24];

    const int N = in_sizes[0] / DIM;
    const int E = in_sizes[1] / 2;
    const int ET = E + N;
    const int* esrc = ei;
    const int* edst = ei + E;

    float *p_xn0, *p_xl, *p_xr, *p_eam, *p_deg, *p_den, *p_sc, *p_agg;
    float *p_s1, *p_s2, *p_s3, *p_s4, *p_h1, *p_oc;
    unsigned* p_smax;
    double* p_st;
    cudaGetSymbolAddress((void**)&p_xn0, g_xn0);
    cudaGetSymbolAddress((void**)&p_xl, g_xl);
    cudaGetSymbolAddress((void**)&p_xr, g_xr);
    cudaGetSymbolAddress((void**)&p_eam, g_eam);
    cudaGetSymbolAddress((void**)&p_deg, g_deg);
    cudaGetSymbolAddress((void**)&p_smax, g_smax);
    cudaGetSymbolAddress((void**)&p_den, g_den);
    cudaGetSymbolAddress((void**)&p_sc, g_sc);
    cudaGetSymbolAddress((void**)&p_agg, g_agg);
    cudaGetSymbolAddress((void**)&p_s1, g_s1);
    cudaGetSymbolAddress((void**)&p_s2, g_s2);
    cudaGetSymbolAddress((void**)&p_s3, g_s3);
    cudaGetSymbolAddress((void**)&p_s4, g_s4);
    cudaGetSymbolAddress((void**)&p_h1, g_h1);
    cudaGetSymbolAddress((void**)&p_oc, g_oc);
    cudaGetSymbolAddress((void**)&p_st, g_stats);

    cudaFuncSetAttribute(score_kernel, cudaFuncAttributeMaxDynamicSharedMemorySize, SCORE_SMEM);

    // zero scratch
    cudaMemsetAsync(p_st, 0, 8 * sizeof(double));
    cudaMemsetAsync(p_deg, 0, (size_t)N * sizeof(float));
    cudaMemsetAsync(p_eam, 0, (size_t)N * DE * sizeof(float));
    cudaMemsetAsync(p_den, 0, (size_t)N * HEADS * sizeof(float));
    cudaMemsetAsync(p_agg, 0, (size_t)N * HD * sizeof(float));
    init_smax_kernel<<<(N * HEADS + 255) / 256, 256>>>(p_smax, N * HEADS);

    // norm0
    stats_kernel<<<1024, 256>>>(x, p_st + 0, N * DIM);
    norm_apply_kernel<<<(N * DIM + 255) / 256, 256>>>(x, p_xn0, nw0, nb0, p_st + 0, N * DIM, DIM);

    // x_l / x_r
    {
        dim3 grid(HD / 64, N / 128);
        gemm_kernel<false, false><<<grid, 256>>>(p_xn0, Wl, bl, nullptr, p_xl, N, HD, DIM);
        gemm_kernel<false, false><<<grid, 256>>>(p_xn0, Wr, br, nullptr, p_xr, N, HD, DIM);
    }

    // self-loop edge attr (scatter-mean)
    degea_kernel<<<(E * DE + 255) / 256, 256>>>(edst, ea, p_eam, p_deg, E);
    eamdiv_kernel<<<(N * DE + 255) / 256, 256>>>(p_eam, p_deg, N * DE);

    // scores + segment max
    score_kernel<<<(ET + EPB - 1) / EPB, 256, SCORE_SMEM>>>(
        p_xl, p_xr, esrc, edst, ea, p_eam, We, att, p_sc, p_smax, E, ET);

    // softmax
    exp_kernel<<<(ET * HEADS + 255) / 256, 256>>>(p_sc, p_smax, p_den, edst, E, ET);
    int write_alpha = (out_size >= N * DOUT + ET * HEADS) ? 1 : 0;
    alpha_kernel<<<(ET * HEADS + 255) / 256, 256>>>(
        p_sc, p_den, edst, (float*)d_out + (size_t)N * DOUT, E, ET, write_alpha);

    // aggregate
    aggregate_kernel<<<(ET * 32 + 255) / 256, 256>>>(p_xl, p_sc, esrc, edst, p_agg, E, ET);

    // head-mean + gat bias + residual
    headmean_kernel<<<(N * DIM + 255) / 256, 256>>>(p_xn0, p_agg, gb, p_s1, N * DIM);

    // norm1
    stats_kernel<<<1024, 256>>>(p_s1, p_st + 2, N * DIM);
    norm_apply_kernel<<<(N * DIM + 255) / 256, 256>>>(p_s1, p_s2, nw1, nb1, p_st + 2, N * DIM, DIM);

    // MLP: relu(s2 @ W1^T + b1) @ W2^T + b2 + s2
    {
        dim3 g1(DHID / 64, N / 128);
        gemm_kernel<true, false><<<g1, 256>>>(p_s2, W1, b1, nullptr, p_h1, N, DHID, DIM);
        dim3 g2(DIM / 64, N / 128);
        gemm_kernel<false, true><<<g2, 256>>>(p_h1, W2, b2, p_s2, p_s3, N, DIM, DHID);
    }

    // norm2
    stats_kernel<<<1024, 256>>>(p_s3, p_st + 4, N * DIM);
    norm_apply_kernel<<<(N * DIM + 255) / 256, 256>>>(p_s3, p_s4, nw2, nb2, p_st + 4, N * DIM, DIM);

    // classifier
    {
        dim3 g(DOUT / 64, N / 128);
        gemm_kernel<false, false><<<g, 256>>>(p_s4, Wc, bc, nullptr, p_oc, N, DOUT, DIM);
    }

    // norm3 -> output
    stats_kernel<<<1024, 256>>>(p_oc, p_st + 6, N * DOUT);
    norm_apply_kernel<<<(N * DOUT + 255) / 256, 256>>>(p_oc, (float*)d_out, nw3, nb3,
                                                       p_st + 6, N * DOUT, DOUT);
}

// round 4
// speedup vs baseline: 1.3661x; 1.3661x over previous
#include <cuda_runtime.h>
#include <cstdint>

// ===================== problem constants =====================
#define DIM    128      // D
#define HEADS  4        // H
#define DE     32       // edge feature dim
#define HD     512      // H*D
#define DHID   2048
#define DOUT   64
#define NMAX   16384
#define EMAX   131072
#define ETMAX  (EMAX + NMAX)
#define EPSN   1e-5f
#define SLOPE  0.2f

// ===================== scratch (static device globals; no allocs) ==========
__device__ float    g_xn0[NMAX * DIM];
__device__ float    g_xl[NMAX * HD];
__device__ float    g_xr[NMAX * HD];
__device__ float    g_eam[NMAX * DE];
__device__ float    g_deg[NMAX];
__device__ unsigned g_smax[NMAX * HEADS];
__device__ float    g_den[NMAX * HEADS];
__device__ float    g_sc[ETMAX * HEADS];
__device__ float    g_agg[NMAX * HD];
__device__ float    g_s1[NMAX * DIM];
__device__ float    g_s2[NMAX * DIM];
__device__ float    g_s3[NMAX * DIM];
__device__ float    g_s4[NMAX * DIM];
__device__ float    g_h1[NMAX * DHID];
__device__ float    g_oc[NMAX * DOUT];
__device__ double   g_stats[8];

// ===================== helpers =====================
__device__ __forceinline__ unsigned fenc(float f) {
    unsigned u = __float_as_uint(f);
    return u ^ ((u >> 31) ? 0xFFFFFFFFu : 0x80000000u);
}
__device__ __forceinline__ float fdec(unsigned u) {
    unsigned v = u ^ ((u >> 31) ? 0x80000000u : 0xFFFFFFFFu);
    return __uint_as_float(v);
}
__device__ __forceinline__ float tf32r(float x) {
    uint32_t r;
    asm("cvt.rna.tf32.f32 %0, %1;" : "=r"(r) : "f"(x));
    return __uint_as_float(r);
}

// ===================== norm stats: sum & sumsq in fp64 =====================
__global__ void stats_kernel(const float* __restrict__ x, double* __restrict__ st, int n) {
    double s = 0.0, s2 = 0.0;
    for (int i = blockIdx.x * blockDim.x + threadIdx.x; i < n; i += gridDim.x * blockDim.x) {
        float v = x[i];
        s += (double)v;
        s2 += (double)v * (double)v;
    }
    __shared__ double sh[256], sh2[256];
    int tid = threadIdx.x;
    sh[tid] = s; sh2[tid] = s2;
    __syncthreads();
    for (int o = 128; o > 0; o >>= 1) {
        if (tid < o) { sh[tid] += sh[tid + o]; sh2[tid] += sh2[tid + o]; }
        __syncthreads();
    }
    if (tid == 0) {
        atomicAdd(&st[0], sh[0]);
        atomicAdd(&st[1], sh2[0]);
    }
}

__global__ void norm_apply_kernel(const float* __restrict__ x, float* __restrict__ y,
                                  const float* __restrict__ w, const float* __restrict__ b,
                                  const double* __restrict__ st, int n, int C) {
    int i = blockIdx.x * blockDim.x + threadIdx.x;
    if (i >= n) return;
    double cnt = (double)n;
    double mu_d = st[0] / cnt;
    double var_d = st[1] / cnt - mu_d * mu_d;
    if (var_d < 0.0) var_d = 0.0;
    float mu = (float)mu_d;
    float inv = 1.0f / ((float)sqrt(var_d) + EPSN);
    int c = i % C;
    y[i] = (x[i] - mu) * inv * w[c] + b[c];
}

// ===================== TF32 tensor-core GEMM: C = A[M,K] * B[N,K]^T + bias ==
// M % 128 == 0, N % 128 == 0, K % 32 == 0 required.
template <bool RELU, bool RES>
__global__ __launch_bounds__(256, 2)
void gemm_tf32_kernel(const float* __restrict__ A, const float* __restrict__ B,
                      const float* __restrict__ bias, const float* __restrict__ res,
                      float* __restrict__ C, int M, int N, int K) {
    constexpr int BM = 128, BN = 128, BK = 32, LDS_ = 36;
    __shared__ float As[BM * LDS_];
    __shared__ float Bs[BN * LDS_];
    int tid = threadIdx.x;
    int wid = tid >> 5, lane = tid & 31;
    int warp_m = wid & 1;      // 2 warps along M -> 64 rows each
    int warp_n = wid >> 1;     // 4 warps along N -> 32 cols each
    int bm = blockIdx.y * BM, bn = blockIdx.x * BN;
    int lq = lane >> 2;        // 0..7
    int lr = lane & 3;         // 0..3

    float acc[4][4][4];
    #pragma unroll
    for (int mi = 0; mi < 4; mi++)
        #pragma unroll
        for (int ni = 0; ni < 4; ni++)
            #pragma unroll
            for (int r = 0; r < 4; r++) acc[mi][ni][r] = 0.f;

    for (int k0 = 0; k0 < K; k0 += BK) {
        // fill As / Bs with tf32-rounded values
        #pragma unroll
        for (int it = 0; it < 4; it++) {
            int idx = it * 256 + tid;
            int r = idx >> 3, c = (idx & 7) << 2;
            float4 v = *(const float4*)(A + (size_t)(bm + r) * K + k0 + c);
            float4 t = make_float4(tf32r(v.x), tf32r(v.y), tf32r(v.z), tf32r(v.w));
            *(float4*)&As[r * LDS_ + c] = t;
        }
        #pragma unroll
        for (int it = 0; it < 4; it++) {
            int idx = it * 256 + tid;
            int r = idx >> 3, c = (idx & 7) << 2;
            float4 v = *(const float4*)(B + (size_t)(bn + r) * K + k0 + c);
            float4 t = make_float4(tf32r(v.x), tf32r(v.y), tf32r(v.z), tf32r(v.w));
            *(float4*)&Bs[r * LDS_ + c] = t;
        }
        __syncthreads();

        #pragma unroll
        for (int kk = 0; kk < BK; kk += 8) {
            uint32_t a[4][4], b[4][2];
            #pragma unroll
            for (int mi = 0; mi < 4; mi++) {
                int row = warp_m * 64 + mi * 16 + lq;
                a[mi][0] = __float_as_uint(As[row * LDS_ + kk + lr]);
                a[mi][1] = __float_as_uint(As[(row + 8) * LDS_ + kk + lr]);
                a[mi][2] = __float_as_uint(As[row * LDS_ + kk + lr + 4]);
                a[mi][3] = __float_as_uint(As[(row + 8) * LDS_ + kk + lr + 4]);
            }
            #pragma unroll
            for (int ni = 0; ni < 4; ni++) {
                int col = warp_n * 32 + ni * 8 + lq;
                b[ni][0] = __float_as_uint(Bs[col * LDS_ + kk + lr]);
                b[ni][1] = __float_as_uint(Bs[col * LDS_ + kk + lr + 4]);
            }
            #pragma unroll
            for (int mi = 0; mi < 4; mi++)
                #pragma unroll
                for (int ni = 0; ni < 4; ni++) {
                    asm volatile(
                        "mma.sync.aligned.m16n8k8.row.col.f32.tf32.tf32.f32 "
                        "{%0,%1,%2,%3}, {%4,%5,%6,%7}, {%8,%9}, {%0,%1,%2,%3};"
                        : "+f"(acc[mi][ni][0]), "+f"(acc[mi][ni][1]),
                          "+f"(acc[mi][ni][2]), "+f"(acc[mi][ni][3])
                        : "r"(a[mi][0]), "r"(a[mi][1]), "r"(a[mi][2]), "r"(a[mi][3]),
                          "r"(b[ni][0]), "r"(b[ni][1]));
                }
        }
        __syncthreads();
    }

    // epilogue
    #pragma unroll
    for (int mi = 0; mi < 4; mi++) {
        int row = bm + warp_m * 64 + mi * 16 + lq;
        #pragma unroll
        for (int ni = 0; ni < 4; ni++) {
            int col = bn + warp_n * 32 + ni * 8 + (lr << 1);
            float b0 = bias[col], b1 = bias[col + 1];
            #pragma unroll
            for (int h = 0; h < 2; h++) {   // h=0 -> row, h=1 -> row+8
                int rr = row + h * 8;
                float v0 = acc[mi][ni][h * 2 + 0] + b0;
                float v1 = acc[mi][ni][h * 2 + 1] + b1;
                if (RELU) { v0 = fmaxf(v0, 0.f); v1 = fmaxf(v1, 0.f); }
                size_t o = (size_t)rr * N + col;
                if (RES) { v0 += res[o]; v1 += res[o + 1]; }
                *(float2*)(C + o) = make_float2(v0, v1);
            }
        }
    }
}

// ===================== SIMT SGEMM (small N: classifier) =====================
template <bool RELU, bool RES>
__global__ void gemm_kernel(const float* __restrict__ A, const float* __restrict__ B,
                            const float* __restrict__ bias, const float* __restrict__ res,
                            float* __restrict__ C, int M, int N, int K) {
    constexpr int BM = 128, BN = 64, BK = 16, TM = 8, TN = 4, THREADS = 256;
    __shared__ float As[BK][BM];
    __shared__ float Bs[BK][BN];
    int tid = threadIdx.x;
    int bm = blockIdx.y * BM, bn = blockIdx.x * BN;
    int tcol = tid & 15;
    int trow = tid >> 4;
    float acc[TM][TN];
    #pragma unroll
    for (int i = 0; i < TM; i++)
        #pragma unroll
        for (int j = 0; j < TN; j++) acc[i][j] = 0.f;

    for (int k0 = 0; k0 < K; k0 += BK) {
        #pragma unroll
        for (int i = tid; i < BM * BK / 4; i += THREADS) {
            int r = i >> 2;
            int c = (i & 3) << 2;
            float4 v = *(const float4*)(A + (size_t)(bm + r) * K + k0 + c);
            As[c + 0][r] = v.x; As[c + 1][r] = v.y; As[c + 2][r] = v.z; As[c + 3][r] = v.w;
        }
        #pragma unroll
        for (int i = tid; i < BN * BK / 4; i += THREADS) {
            int r = i >> 2;
            int c = (i & 3) << 2;
            float4 v = *(const float4*)(B + (size_t)(bn + r) * K + k0 + c);
            Bs[c + 0][r] = v.x; Bs[c + 1][r] = v.y; Bs[c + 2][r] = v.z; Bs[c + 3][r] = v.w;
        }
        __syncthreads();
        #pragma unroll
        for (int k = 0; k < BK; k++) {
            float4 a0 = *(const float4*)&As[k][trow * TM];
            float4 a1 = *(const float4*)&As[k][trow * TM + 4];
            float4 b0 = *(const float4*)&Bs[k][tcol * TN];
            float av[TM] = {a0.x, a0.y, a0.z, a0.w, a1.x, a1.y, a1.z, a1.w};
            float bv[TN] = {b0.x, b0.y, b0.z, b0.w};
            #pragma unroll
            for (int i = 0; i < TM; i++)
                #pragma unroll
                for (int j = 0; j < TN; j++) acc[i][j] += av[i] * bv[j];
        }
        __syncthreads();
    }
    int row0 = bm + trow * TM;
    int col0 = bn + tcol * TN;
    #pragma unroll
    for (int i = 0; i < TM; i++) {
        size_t base = (size_t)(row0 + i) * N + col0;
        #pragma unroll
        for (int j = 0; j < TN; j++) {
            float v = acc[i][j] + bias[col0 + j];
            if (RELU) v = v > 0.f ? v : 0.f;
            if (RES) v += res[base + j];
            C[base + j] = v;
        }
    }
}

// ===================== GAT edge kernels =====================
__global__ void degea_kernel(const int* __restrict__ edst, const float* __restrict__ ea,
                             float* __restrict__ eam, float* __restrict__ deg, int E) {
    int i = blockIdx.x * blockDim.x + threadIdx.x;
    if (i >= E * DE) return;
    int e = i >> 5, k = i & 31;
    int d = __ldg(edst + e);
    atomicAdd(&eam[d * DE + k], ea[i]);
    if (k == 0) atomicAdd(&deg[d], 1.f);
}

__global__ void eamdiv_kernel(float* __restrict__ eam, const float* __restrict__ deg, int n32) {
    int i = blockIdx.x * blockDim.x + threadIdx.x;
    if (i >= n32) return;
    eam[i] *= 1.f / fmaxf(deg[i >> 5], 1.f);
}

__global__ void init_smax_kernel(unsigned* __restrict__ smax, int n) {
    int i = blockIdx.x * blockDim.x + threadIdx.x;
    if (i < n) smax[i] = 0x007FFFFFu;  // fenc(-inf)
}

// per-edge fused:  z = lrelu(xl[src] + xr[dst] + ea@We^T); score = z . att  (per head)
#define EPB 16
#define SCORE_SMEM (512 * 36 * 4 + 512 * 4 + EPB * 32 * 4)
__global__ void score_kernel(const float* __restrict__ XL, const float* __restrict__ XR,
                             const int* __restrict__ esrc, const int* __restrict__ edst,
                             const float* __restrict__ eattr, const float* __restrict__ eam,
                             const float* __restrict__ We, const float* __restrict__ att,
                             float* __restrict__ SC, unsigned* __restrict__ SMAX,
                             int E, int ET) {
    extern __shared__ float sm[];
    float* We_s = sm;                    // 512 rows x (32 data + 4 pad) floats
    float* att_s = sm + 512 * 36;        // 512
    float* ea_s = att_s + 512;           // EPB * 32
    __shared__ int src_s[EPB], dst_s[EPB];
    __shared__ float sc_s[HEADS];
    int tid = threadIdx.x;
    const float4* We4 = (const float4*)We;
    float4* Ws4 = (float4*)We_s;
    for (int i = tid; i < 512 * 8; i += 256) {
        int r = i >> 3, k4 = i & 7;
        Ws4[r * 9 + k4] = We4[i];
    }
    for (int i = tid; i < 512; i += 256) att_s[i] = att[i];
    int e0 = blockIdx.x * EPB;
    for (int i = tid; i < EPB * 32; i += 256) {
        int el = i >> 5, k = i & 31;
        int e = e0 + el;
        float v = 0.f;
        if (e < ET) v = (e < E) ? eattr[(size_t)e * DE + k] : eam[(size_t)(e - E) * DE + k];
        ea_s[el * 32 + k] = v;
    }
    if (tid < EPB) {
        int e = e0 + tid;
        if (e < ET) {
            src_s[tid] = (e < E) ? esrc[e] : (e - E);
            dst_s[tid] = (e < E) ? edst[e] : (e - E);
        }
    }
    __syncthreads();
    int lane = tid & 31;
    int h0 = tid >> 7;  // warp-uniform
    for (int ee = 0; ee < EPB; ee++) {
        int e = e0 + ee;
        if (e >= ET) break;
        if (tid < HEADS) sc_s[tid] = 0.f;
        __syncthreads();
        int s = src_s[ee], d = dst_s[ee];
        const float4* ea4 = (const float4*)(ea_s + ee * 32);
        float c0v = 0.f, c1v = 0.f;
        #pragma unroll
        for (int p = 0; p < 2; p++) {
            int idx = tid + p * 256;
            float v = __ldg(XL + (size_t)s * HD + idx) + __ldg(XR + (size_t)d * HD + idx);
            float4 acc = make_float4(0.f, 0.f, 0.f, 0.f);
            #pragma unroll
            for (int k4 = 0; k4 < 8; k4++) {
                float4 w = Ws4[idx * 9 + k4];
                float4 a = ea4[k4];
                acc.x += w.x * a.x; acc.y += w.y * a.y;
                acc.z += w.z * a.z; acc.w += w.w * a.w;
            }
            v += acc.x + acc.y + acc.z + acc.w;
            v = v > 0.f ? v : SLOPE * v;
            float c = v * att_s[idx];
            if (p == 0) c0v = c; else c1v = c;
        }
        #pragma unroll
        for (int o = 16; o > 0; o >>= 1) {
            c0v += __shfl_down_sync(0xFFFFFFFFu, c0v, o);
            c1v += __shfl_down_sync(0xFFFFFFFFu, c1v, o);
        }
        if (lane == 0) {
            atomicAdd(&sc_s[h0], c0v);
            atomicAdd(&sc_s[h0 + 2], c1v);
        }
        __syncthreads();
        if (tid < HEADS) {
            float sv = sc_s[tid];
            SC[(size_t)e * HEADS + tid] = sv;
            atomicMax(&SMAX[(size_t)d * HEADS + tid], fenc(sv));
        }
    }
}

__global__ void exp_kernel(float* __restrict__ SC, const unsigned* __restrict__ SMAX,
                           float* __restrict__ den, const int* __restrict__ edst,
                           int E, int ET) {
    int i = blockIdx.x * blockDim.x + threadIdx.x;
    if (i >= ET * HEADS) return;
    int e = i >> 2, h = i & 3;
    int d = (e < E) ? __ldg(edst + e) : (e - E);
    float m = fdec(SMAX[d * HEADS + h]);
    float ex = expf(SC[i] - m);
    SC[i] = ex;
    atomicAdd(&den[d * HEADS + h], ex);
}

__global__ void alpha_kernel(float* __restrict__ SC, const float* __restrict__ den,
                             const int* __restrict__ edst, float* __restrict__ out_alpha,
                             int E, int ET, int write_out) {
    int i = blockIdx.x * blockDim.x + threadIdx.x;
    if (i >= ET * HEADS) return;
    int e = i >> 2, h = i & 3;
    int d = (e < E) ? __ldg(edst + e) : (e - E);
    float a = SC[i] / den[d * HEADS + h];
    SC[i] = a;
    if (write_out) out_alpha[i] = a;
}

// one warp per edge: AGG[dst] += XL[src] * alpha  (512 floats as 16 red.v4 per lane-group)
__global__ void aggregate_kernel(const float* __restrict__ XL, const float* __restrict__ SC,
                                 const int* __restrict__ esrc, const int* __restrict__ edst,
                                 float* __restrict__ AGG, int E, int ET) {
    int warp = (blockIdx.x * blockDim.x + threadIdx.x) >> 5;
    int lane = threadIdx.x & 31;
    if (warp >= ET) return;
    int e = warp;
    int s = (e < E) ? __ldg(esrc + e) : (e - E);
    int d = (e < E) ? __ldg(edst + e) : (e - E);
    float4 al = *(const float4*)(SC + (size_t)e * HEADS);
    float alph[4] = {al.x, al.y, al.z, al.w};
    const float4* xl4 = (const float4*)(XL + (size_t)s * HD);
    float* base = AGG + (size_t)d * HD;
    #pragma unroll
    for (int j = 0; j < 4; j++) {
        int i4 = lane + 32 * j;           // float4 index 0..127
        float a = alph[i4 >> 5];          // head, uniform within a float4
        float4 v = __ldg(xl4 + i4);
        float* p = base + i4 * 4;
        asm volatile("red.global.add.v4.f32 [%0], {%1,%2,%3,%4};"
                     :: "l"(p), "f"(v.x * a), "f"(v.y * a), "f"(v.z * a), "f"(v.w * a)
                     : "memory");
    }
}

__global__ void headmean_kernel(const float* __restrict__ xn0, const float* __restrict__ agg,
                                const float* __restrict__ gb, float* __restrict__ s1, int total) {
    int i = blockIdx.x * blockDim.x + threadIdx.x;
    if (i >= total) return;
    int c = i & 127;
    int n = i >> 7;
    const float* a = agg + (size_t)n * HD;
    s1[i] = xn0[i] + 0.25f * (a[c] + a[c + 128] + a[c + 256] + a[c + 384]) + gb[c];
}

// ===================== launch =====================
extern "C" void kernel_launch(void* const* d_in, const int* in_sizes, int n_in,
                              void* d_out, int out_size) {
    const float* x   = (const float*)d_in[0];
    const int* ei    = (const int*)d_in[1];
    const float* ea  = (const float*)d_in[2];
    // d_in[3] = batch (unused, all zeros)
    const float* Wl  = (const float*)d_in[4];
    const float* bl  = (const float*)d_in[5];
    const float* Wr  = (const float*)d_in[6];
    const float* br  = (const float*)d_in[7];
    const float* We  = (const float*)d_in[8];
    const float* att = (const float*)d_in[9];
    const float* gb  = (const float*)d_in[10];
    const float* W1  = (const float*)d_in[11];
    const float* b1  = (const float*)d_in[12];
    const float* W2  = (const float*)d_in[13];
    const float* b2  = (const float*)d_in[14];
    const float* Wc  = (const float*)d_in[15];
    const float* bc  = (const float*)d_in[16];
    const float* nw0 = (const float*)d_in[17];
    const float* nb0 = (const float*)d_in[18];
    const float* nw1 = (const float*)d_in[19];
    const float* nb1 = (const float*)d_in[20];
    const float* nw2 = (const float*)d_in[21];
    const float* nb2 = (const float*)d_in[22];
    const float* nw3 = (const float*)d_in[23];
    const float* nb3 = (const float*)d_in[24];

    const int N = in_sizes[0] / DIM;
    const int E = in_sizes[1] / 2;
    const int ET = E + N;
    const int* esrc = ei;
    const int* edst = ei + E;

    float *p_xn0, *p_xl, *p_xr, *p_eam, *p_deg, *p_den, *p_sc, *p_agg;
    float *p_s1, *p_s2, *p_s3, *p_s4, *p_h1, *p_oc;
    unsigned* p_smax;
    double* p_st;
    cudaGetSymbolAddress((void**)&p_xn0, g_xn0);
    cudaGetSymbolAddress((void**)&p_xl, g_xl);
    cudaGetSymbolAddress((void**)&p_xr, g_xr);
    cudaGetSymbolAddress((void**)&p_eam, g_eam);
    cudaGetSymbolAddress((void**)&p_deg, g_deg);
    cudaGetSymbolAddress((void**)&p_smax, g_smax);
    cudaGetSymbolAddress((void**)&p_den, g_den);
    cudaGetSymbolAddress((void**)&p_sc, g_sc);
    cudaGetSymbolAddress((void**)&p_agg, g_agg);
    cudaGetSymbolAddress((void**)&p_s1, g_s1);
    cudaGetSymbolAddress((void**)&p_s2, g_s2);
    cudaGetSymbolAddress((void**)&p_s3, g_s3);
    cudaGetSymbolAddress((void**)&p_s4, g_s4);
    cudaGetSymbolAddress((void**)&p_h1, g_h1);
    cudaGetSymbolAddress((void**)&p_oc, g_oc);
    cudaGetSymbolAddress((void**)&p_st, g_stats);

    cudaFuncSetAttribute(score_kernel, cudaFuncAttributeMaxDynamicSharedMemorySize, SCORE_SMEM);

    // zero scratch
    cudaMemsetAsync(p_st, 0, 8 * sizeof(double));
    cudaMemsetAsync(p_deg, 0, (size_t)N * sizeof(float));
    cudaMemsetAsync(p_eam, 0, (size_t)N * DE * sizeof(float));
    cudaMemsetAsync(p_den, 0, (size_t)N * HEADS * sizeof(float));
    cudaMemsetAsync(p_agg, 0, (size_t)N * HD * sizeof(float));
    init_smax_kernel<<<(N * HEADS + 255) / 256, 256>>>(p_smax, N * HEADS);

    // norm0
    stats_kernel<<<1024, 256>>>(x, p_st + 0, N * DIM);
    norm_apply_kernel<<<(N * DIM + 255) / 256, 256>>>(x, p_xn0, nw0, nb0, p_st + 0, N * DIM, DIM);

    // x_l / x_r  (TF32 tensor cores)
    {
        dim3 grid(HD / 128, N / 128);
        gemm_tf32_kernel<false, false><<<grid, 256>>>(p_xn0, Wl, bl, nullptr, p_xl, N, HD, DIM);
        gemm_tf32_kernel<false, false><<<grid, 256>>>(p_xn0, Wr, br, nullptr, p_xr, N, HD, DIM);
    }

    // self-loop edge attr (scatter-mean)
    degea_kernel<<<(E * DE + 255) / 256, 256>>>(edst, ea, p_eam, p_deg, E);
    eamdiv_kernel<<<(N * DE + 255) / 256, 256>>>(p_eam, p_deg, N * DE);

    // scores + segment max
    score_kernel<<<(ET + EPB - 1) / EPB, 256, SCORE_SMEM>>>(
        p_xl, p_xr, esrc, edst, ea, p_eam, We, att, p_sc, p_smax, E, ET);

    // softmax
    exp_kernel<<<(ET * HEADS + 255) / 256, 256>>>(p_sc, p_smax, p_den, edst, E, ET);
    int write_alpha = (out_size >= N * DOUT + ET * HEADS) ? 1 : 0;
    alpha_kernel<<<(ET * HEADS + 255) / 256, 256>>>(
        p_sc, p_den, edst, (float*)d_out + (size_t)N * DOUT, E, ET, write_alpha);

    // aggregate
    aggregate_kernel<<<(ET * 32 + 255) / 256, 256>>>(p_xl, p_sc, esrc, edst, p_agg, E, ET);

    // head-mean + gat bias + residual
    headmean_kernel<<<(N * DIM + 255) / 256, 256>>>(p_xn0, p_agg, gb, p_s1, N * DIM);

    // norm1
    stats_kernel<<<1024, 256>>>(p_s1, p_st + 2, N * DIM);
    norm_apply_kernel<<<(N * DIM + 255) / 256, 256>>>(p_s1, p_s2, nw1, nb1, p_st + 2, N * DIM, DIM);

    // MLP: relu(s2 @ W1^T + b1) @ W2^T + b2 + s2   (TF32 tensor cores)
    {
        dim3 g1(DHID / 128, N / 128);
        gemm_tf32_kernel<true, false><<<g1, 256>>>(p_s2, W1, b1, nullptr, p_h1, N, DHID, DIM);
        dim3 g2(DIM / 128, N / 128);
        gemm_tf32_kernel<false, true><<<g2, 256>>>(p_h1, W2, b2, p_s2, p_s3, N, DIM, DHID);
    }

    // norm2
    stats_kernel<<<1024, 256>>>(p_s3, p_st + 4, N * DIM);
    norm_apply_kernel<<<(N * DIM + 255) / 256, 256>>>(p_s3, p_s4, nw2, nb2, p_st + 4, N * DIM, DIM);

    // classifier (N=64 -> SIMT kernel)
    {
        dim3 g(DOUT / 64, N / 128);
        gemm_kernel<false, false><<<g, 256>>>(p_s4, Wc, bc, nullptr, p_oc, N, DOUT, DIM);
    }

    // norm3 -> output
    stats_kernel<<<1024, 256>>>(p_oc, p_st + 6, N * DOUT);
    norm_apply_kernel<<<(N * DOUT + 255) / 256, 256>>>(p_oc, (float*)d_out, nw3, nb3,
                                                       p_st + 6, N * DOUT, DOUT);
}

// round 7
// speedup vs baseline: 1.9920x; 1.4582x over previous
#include <cuda_runtime.h>
#include <cstdint>

// ===================== problem constants =====================
#define DIM    128      // D
#define HEADS  4        // H
#define DE     32       // edge feature dim
#define HD     512      // H*D
#define DHID   2048
#define DOUT   64
#define NMAX   16384
#define EMAX   131072
#define ETMAX  (EMAX + NMAX)
#define EPSN   1e-5f
#define SLOPE  0.2f

// ===================== scratch (static device globals; no allocs) ==========
__device__ float    g_xn0[NMAX * DIM];
__device__ float    g_xl[NMAX * HD];
__device__ float    g_xr[NMAX * HD];
__device__ float    g_eam[NMAX * DE];
__device__ float    g_deg[NMAX];
__device__ unsigned g_smax[NMAX * HEADS];
__device__ float    g_den[NMAX * HEADS];
__device__ float    g_sc[ETMAX * HEADS];
__device__ float    g_agg[NMAX * DIM];     // head-mixed: N x 128
__device__ float    g_s1[NMAX * DIM];
__device__ float    g_s2[NMAX * DIM];
__device__ float    g_s3[NMAX * DIM];
__device__ float    g_s4[NMAX * DIM];
__device__ float    g_h1[NMAX * DHID];
__device__ float    g_oc[NMAX * DOUT];
__device__ double   g_stats[8];

// ===================== helpers =====================
__device__ __forceinline__ unsigned fenc(float f) {
    unsigned u = __float_as_uint(f);
    return u ^ ((u >> 31) ? 0xFFFFFFFFu : 0x80000000u);
}
__device__ __forceinline__ float fdec(unsigned u) {
    unsigned v = u ^ ((u >> 31) ? 0x80000000u : 0xFFFFFFFFu);
    return __uint_as_float(v);
}
__device__ __forceinline__ float tf32r(float x) {
    uint32_t r;
    asm("cvt.rna.tf32.f32 %0, %1;" : "=r"(r) : "f"(x));
    return __uint_as_float(r);
}

// ===================== norm stats: sum & sumsq in fp64 =====================
__global__ void stats_kernel(const float* __restrict__ x, double* __restrict__ st, int n) {
    double s = 0.0, s2 = 0.0;
    for (int i = blockIdx.x * blockDim.x + threadIdx.x; i < n; i += gridDim.x * blockDim.x) {
        float v = x[i];
        s += (double)v;
        s2 += (double)v * (double)v;
    }
    __shared__ double sh[256], sh2[256];
    int tid = threadIdx.x;
    sh[tid] = s; sh2[tid] = s2;
    __syncthreads();
    for (int o = 128; o > 0; o >>= 1) {
        if (tid < o) { sh[tid] += sh[tid + o]; sh2[tid] += sh2[tid + o]; }
        __syncthreads();
    }
    if (tid == 0) {
        atomicAdd(&st[0], sh[0]);
        atomicAdd(&st[1], sh2[0]);
    }
}

__global__ void norm_apply_kernel(const float* __restrict__ x, float* __restrict__ y,
                                  const float* __restrict__ w, const float* __restrict__ b,
                                  const double* __restrict__ st, int n, int C) {
    int i = blockIdx.x * blockDim.x + threadIdx.x;
    if (i >= n) return;
    double cnt = (double)n;
    double mu_d = st[0] / cnt;
    double var_d = st[1] / cnt - mu_d * mu_d;
    if (var_d < 0.0) var_d = 0.0;
    float mu = (float)mu_d;
    float inv = 1.0f / ((float)sqrt(var_d) + EPSN);
    int c = i % C;
    y[i] = (x[i] - mu) * inv * w[c] + b[c];
}

// ===================== TF32 tensor-core GEMM: C = A[M,K] * B[N,K]^T + bias ==
template <bool RELU, bool RES>
__global__ __launch_bounds__(256, 2)
void gemm_tf32_kernel(const float* __restrict__ A, const float* __restrict__ B,
                      const float* __restrict__ bias, const float* __restrict__ res,
                      float* __restrict__ C, int M, int N, int K) {
    constexpr int BM = 128, BN = 128, BK = 32, LDS_ = 36;
    __shared__ float As[BM * LDS_];
    __shared__ float Bs[BN * LDS_];
    int tid = threadIdx.x;
    int wid = tid >> 5, lane = tid & 31;
    int warp_m = wid & 1;
    int warp_n = wid >> 1;
    int bm = blockIdx.y * BM, bn = blockIdx.x * BN;
    int lq = lane >> 2;
    int lr = lane & 3;

    float acc[4][4][4];
    #pragma unroll
    for (int mi = 0; mi < 4; mi++)
        #pragma unroll
        for (int ni = 0; ni < 4; ni++)
            #pragma unroll
            for (int r = 0; r < 4; r++) acc[mi][ni][r] = 0.f;

    for (int k0 = 0; k0 < K; k0 += BK) {
        #pragma unroll
        for (int it = 0; it < 4; it++) {
            int idx = it * 256 + tid;
            int r = idx >> 3, c = (idx & 7) << 2;
            float4 v = *(const float4*)(A + (size_t)(bm + r) * K + k0 + c);
            float4 t = make_float4(tf32r(v.x), tf32r(v.y), tf32r(v.z), tf32r(v.w));
            *(float4*)&As[r * LDS_ + c] = t;
        }
        #pragma unroll
        for (int it = 0; it < 4; it++) {
            int idx = it * 256 + tid;
            int r = idx >> 3, c = (idx & 7) << 2;
            float4 v = *(const float4*)(B + (size_t)(bn + r) * K + k0 + c);
            float4 t = make_float4(tf32r(v.x), tf32r(v.y), tf32r(v.z), tf32r(v.w));
            *(float4*)&Bs[r * LDS_ + c] = t;
        }
        __syncthreads();

        #pragma unroll
        for (int kk = 0; kk < BK; kk += 8) {
            uint32_t a[4][4], b[4][2];
            #pragma unroll
            for (int mi = 0; mi < 4; mi++) {
                int row = warp_m * 64 + mi * 16 + lq;
                a[mi][0] = __float_as_uint(As[row * LDS_ + kk + lr]);
                a[mi][1] = __float_as_uint(As[(row + 8) * LDS_ + kk + lr]);
                a[mi][2] = __float_as_uint(As[row * LDS_ + kk + lr + 4]);
                a[mi][3] = __float_as_uint(As[(row + 8) * LDS_ + kk + lr + 4]);
            }
            #pragma unroll
            for (int ni = 0; ni < 4; ni++) {
                int col = warp_n * 32 + ni * 8 + lq;
                b[ni][0] = __float_as_uint(Bs[col * LDS_ + kk + lr]);
                b[ni][1] = __float_as_uint(Bs[col * LDS_ + kk + lr + 4]);
            }
            #pragma unroll
            for (int mi = 0; mi < 4; mi++)
                #pragma unroll
                for (int ni = 0; ni < 4; ni++) {
                    asm volatile(
                        "mma.sync.aligned.m16n8k8.row.col.f32.tf32.tf32.f32 "
                        "{%0,%1,%2,%3}, {%4,%5,%6,%7}, {%8,%9}, {%0,%1,%2,%3};"
                        : "+f"(acc[mi][ni][0]), "+f"(acc[mi][ni][1]),
                          "+f"(acc[mi][ni][2]), "+f"(acc[mi][ni][3])
                        : "r"(a[mi][0]), "r"(a[mi][1]), "r"(a[mi][2]), "r"(a[mi][3]),
                          "r"(b[ni][0]), "r"(b[ni][1]));
                }
        }
        __syncthreads();
    }

    #pragma unroll
    for (int mi = 0; mi < 4; mi++) {
        int row = bm + warp_m * 64 + mi * 16 + lq;
        #pragma unroll
        for (int ni = 0; ni < 4; ni++) {
            int col = bn + warp_n * 32 + ni * 8 + (lr << 1);
            float b0 = bias[col], b1 = bias[col + 1];
            #pragma unroll
            for (int h = 0; h < 2; h++) {
                int rr = row + h * 8;
                float v0 = acc[mi][ni][h * 2 + 0] + b0;
                float v1 = acc[mi][ni][h * 2 + 1] + b1;
                if (RELU) { v0 = fmaxf(v0, 0.f); v1 = fmaxf(v1, 0.f); }
                size_t o = (size_t)rr * N + col;
                if (RES) { v0 += res[o]; v1 += res[o + 1]; }
                *(float2*)(C + o) = make_float2(v0, v1);
            }
        }
    }
}

// ===================== SIMT SGEMM (small N: classifier) =====================
template <bool RELU, bool RES>
__global__ void gemm_kernel(const float* __restrict__ A, const float* __restrict__ B,
                            const float* __restrict__ bias, const float* __restrict__ res,
                            float* __restrict__ C, int M, int N, int K) {
    constexpr int BM = 128, BN = 64, BK = 16, TM = 8, TN = 4, THREADS = 256;
    __shared__ float As[BK][BM];
    __shared__ float Bs[BK][BN];
    int tid = threadIdx.x;
    int bm = blockIdx.y * BM, bn = blockIdx.x * BN;
    int tcol = tid & 15;
    int trow = tid >> 4;
    float acc[TM][TN];
    #pragma unroll
    for (int i = 0; i < TM; i++)
        #pragma unroll
        for (int j = 0; j < TN; j++) acc[i][j] = 0.f;

    for (int k0 = 0; k0 < K; k0 += BK) {
        #pragma unroll
        for (int i = tid; i < BM * BK / 4; i += THREADS) {
            int r = i >> 2;
            int c = (i & 3) << 2;
            float4 v = *(const float4*)(A + (size_t)(bm + r) * K + k0 + c);
            As[c + 0][r] = v.x; As[c + 1][r] = v.y; As[c + 2][r] = v.z; As[c + 3][r] = v.w;
        }
        #pragma unroll
        for (int i = tid; i < BN * BK / 4; i += THREADS) {
            int r = i >> 2;
            int c = (i & 3) << 2;
            float4 v = *(const float4*)(B + (size_t)(bn + r) * K + k0 + c);
            Bs[c + 0][r] = v.x; Bs[c + 1][r] = v.y; Bs[c + 2][r] = v.z; Bs[c + 3][r] = v.w;
        }
        __syncthreads();
        #pragma unroll
        for (int k = 0; k < BK; k++) {
            float4 a0 = *(const float4*)&As[k][trow * TM];
            float4 a1 = *(const float4*)&As[k][trow * TM + 4];
            float4 b0 = *(const float4*)&Bs[k][tcol * TN];
            float av[TM] = {a0.x, a0.y, a0.z, a0.w, a1.x, a1.y, a1.z, a1.w};
            float bv[TN] = {b0.x, b0.y, b0.z, b0.w};
            #pragma unroll
            for (int i = 0; i < TM; i++)
                #pragma unroll
                for (int j = 0; j < TN; j++) acc[i][j] += av[i] * bv[j];
        }
        __syncthreads();
    }
    int row0 = bm + trow * TM;
    int col0 = bn + tcol * TN;
    #pragma unroll
    for (int i = 0; i < TM; i++) {
        size_t base = (size_t)(row0 + i) * N + col0;
        #pragma unroll
        for (int j = 0; j < TN; j++) {
            float v = acc[i][j] + bias[col0 + j];
            if (RELU) v = v > 0.f ? v : 0.f;
            if (RES) v += res[base + j];
            C[base + j] = v;
        }
    }
}

// ===================== GAT edge kernels =====================
// vectorized scatter-mean accumulation: one thread per (edge, k4)
__global__ void degea_kernel(const int* __restrict__ edst, const float* __restrict__ ea,
                             float* __restrict__ eam, float* __restrict__ deg, int E) {
    int i = blockIdx.x * blockDim.x + threadIdx.x;
    if (i >= E * 8) return;
    int e = i >> 3, k4 = i & 7;
    int d = __ldg(edst + e);
    float4 v = *(const float4*)(ea + (size_t)e * DE + k4 * 4);
    float* p = eam + (size_t)d * DE + k4 * 4;
    asm volatile("red.global.add.v4.f32 [%0], {%1,%2,%3,%4};"
                 :: "l"(p), "f"(v.x), "f"(v.y), "f"(v.z), "f"(v.w) : "memory");
    if (k4 == 0) {
        float* q = deg + d;
        asm volatile("red.global.add.f32 [%0], %1;" :: "l"(q), "f"(1.0f) : "memory");
    }
}

__global__ void eamdiv_kernel(float* __restrict__ eam, const float* __restrict__ deg, int n32) {
    int i = blockIdx.x * blockDim.x + threadIdx.x;
    if (i >= n32) return;
    eam[i] *= 1.f / fmaxf(deg[i >> 5], 1.f);
}

__global__ void init_smax_kernel(unsigned* __restrict__ smax, int n) {
    int i = blockIdx.x * blockDim.x + threadIdx.x;
    if (i < n) smax[i] = 0x007FFFFFu;  // fenc(-inf)
}

// ===================== warp-per-edge score kernel =====================
// z = lrelu(xl[src] + xr[dst] + ea@We^T); score_h = z_h . att_h
#define SC_WARPS 8
#define SC_SMEM ((512 * 36 + 512 + SC_WARPS * 32) * 4)
__global__ __launch_bounds__(256)
void score_warp_kernel(const float* __restrict__ XL, const float* __restrict__ XR,
                       const int* __restrict__ esrc, const int* __restrict__ edst,
                       const float* __restrict__ eattr, const float* __restrict__ eam,
                       const float* __restrict__ We, const float* __restrict__ att,
                       float* __restrict__ SC, unsigned* __restrict__ SMAX,
                       int E, int ET, int nwarps_total) {
    extern __shared__ float sm[];
    float* We_s = sm;                       // 512 rows x 36 (padded)
    float* att_s = sm + 512 * 36;           // 512
    float* ea_s = att_s + 512;              // SC_WARPS * 32
    int tid = threadIdx.x;
    int wid = tid >> 5, lane = tid & 31;

    const float4* We4 = (const float4*)We;
    float4* Ws4 = (float4*)We_s;
    for (int i = tid; i < 512 * 8; i += 256)
        Ws4[(i >> 3) * 9 + (i & 7)] = We4[i];
    for (int i = tid; i < 512; i += 256) att_s[i] = att[i];
    __syncthreads();

    float* eaw = ea_s + wid * 32;
    int gw = blockIdx.x * SC_WARPS + wid;
    for (int e = gw; e < ET; e += nwarps_total) {
        int s, d;
        const float* eaptr;
        if (e < E) {
            s = __ldg(esrc + e); d = __ldg(edst + e);
            eaptr = eattr + (size_t)e * DE;
        } else {
            s = d = e - E;
            eaptr = eam + (size_t)(e - E) * DE;
        }
        eaw[lane] = __ldg(eaptr + lane);
        __syncwarp();
        // ea row into registers (broadcast reads, conflict-free)
        float4 ea0 = *(const float4*)(eaw + 0);
        float4 ea1 = *(const float4*)(eaw + 4);
        float4 ea2 = *(const float4*)(eaw + 8);
        float4 ea3 = *(const float4*)(eaw + 12);
        float4 ea4v = *(const float4*)(eaw + 16);
        float4 ea5 = *(const float4*)(eaw + 20);
        float4 ea6 = *(const float4*)(eaw + 24);
        float4 ea7 = *(const float4*)(eaw + 28);

        const float* xlp = XL + (size_t)s * HD;
        const float* xrp = XR + (size_t)d * HD;
        float ah[4] = {0.f, 0.f, 0.f, 0.f};
        #pragma unroll
        for (int j = 0; j < 16; j++) {
            int idx = lane + 32 * j;
            float v = __ldg(xlp + idx) + __ldg(xrp + idx);
            const float4* w4 = (const float4*)(We_s + idx * 36);
            float4 w;
            float acc = 0.f;
            w = w4[0]; acc += w.x * ea0.x + w.y * ea0.y + w.z * ea0.z + w.w * ea0.w;
            w = w4[1]; acc += w.x * ea1.x + w.y * ea1.y + w.z * ea1.z + w.w * ea1.w;
            w = w4[2]; acc += w.x * ea2.x + w.y * ea2.y + w.z * ea2.z + w.w * ea2.w;
            w = w4[3]; acc += w.x * ea3.x + w.y * ea3.y + w.z * ea3.z + w.w * ea3.w;
            w = w4[4]; acc += w.x * ea4v.x + w.y * ea4v.y + w.z * ea4v.z + w.w * ea4v.w;
            w = w4[5]; acc += w.x * ea5.x + w.y * ea5.y + w.z * ea5.z + w.w * ea5.w;
            w = w4[6]; acc += w.x * ea6.x + w.y * ea6.y + w.z * ea6.z + w.w * ea6.w;
            w = w4[7]; acc += w.x * ea7.x + w.y * ea7.y + w.z * ea7.z + w.w * ea7.w;
            v += acc;
            v = v > 0.f ? v : SLOPE * v;
            ah[j >> 2] += v * att_s[idx];
        }
        #pragma unroll
        for (int h = 0; h < 4; h++) {
            float v = ah[h];
            #pragma unroll
            for (int o = 16; o > 0; o >>= 1) v += __shfl_down_sync(0xFFFFFFFFu, v, o);
            if (lane == 0) {
                SC[(size_t)e * HEADS + h] = v;
                atomicMax(&SMAX[(size_t)d * HEADS + h], fenc(v));
            }
        }
        __syncwarp();
    }
}

__global__ void exp_kernel(float* __restrict__ SC, const unsigned* __restrict__ SMAX,
                           float* __restrict__ den, const int* __restrict__ edst,
                           int E, int ET) {
    int i = blockIdx.x * blockDim.x + threadIdx.x;
    if (i >= ET * HEADS) return;
    int e = i >> 2, h = i & 3;
    int d = (e < E) ? __ldg(edst + e) : (e - E);
    float m = fdec(SMAX[d * HEADS + h]);
    float ex = expf(SC[i] - m);
    SC[i] = ex;
    atomicAdd(&den[d * HEADS + h], ex);
}

__global__ void alpha_kernel(float* __restrict__ SC, const float* __restrict__ den,
                             const int* __restrict__ edst, float* __restrict__ out_alpha,
                             int E, int ET, int write_out) {
    int i = blockIdx.x * blockDim.x + threadIdx.x;
    if (i >= ET * HEADS) return;
    int e = i >> 2, h = i & 3;
    int d = (e < E) ? __ldg(edst + e) : (e - E);
    float a = SC[i] / den[d * HEADS + h];
    SC[i] = a;
    if (write_out) out_alpha[i] = a;
}

// one warp per edge, head-mixed: AGG[dst,c] += sum_h alpha_h * XL[src, h*128+c]
__global__ void aggregate_kernel(const float* __restrict__ XL, const float* __restrict__ SC,
                                 const int* __restrict__ esrc, const int* __restrict__ edst,
                                 float* __restrict__ AGG, int E, int ET) {
    int warp = (blockIdx.x * blockDim.x + threadIdx.x) >> 5;
    int lane = threadIdx.x & 31;
    if (warp >= ET) return;
    int e = warp;
    int s = (e < E) ? __ldg(esrc + e) : (e - E);
    int d = (e < E) ? __ldg(edst + e) : (e - E);
    float4 al = *(const float4*)(SC + (size_t)e * HEADS);
    const float4* xl4 = (const float4*)(XL + (size_t)s * HD);
    float4 v0 = __ldg(xl4 + 0 * 32 + lane);
    float4 v1 = __ldg(xl4 + 1 * 32 + lane);
    float4 v2 = __ldg(xl4 + 2 * 32 + lane);
    float4 v3 = __ldg(xl4 + 3 * 32 + lane);
    float rx = al.x * v0.x + al.y * v1.x + al.z * v2.x + al.w * v3.x;
    float ry = al.x * v0.y + al.y * v1.y + al.z * v2.y + al.w * v3.y;
    float rz = al.x * v0.z + al.y * v1.z + al.z * v2.z + al.w * v3.z;
    float rw = al.x * v0.w + al.y * v1.w + al.z * v2.w + al.w * v3.w;
    float* p = AGG + (size_t)d * DIM + lane * 4;
    asm volatile("red.global.add.v4.f32 [%0], {%1,%2,%3,%4};"
                 :: "l"(p), "f"(rx), "f"(ry), "f"(rz), "f"(rw) : "memory");
}

__global__ void headmean_kernel(const float* __restrict__ xn0, const float* __restrict__ agg,
                                const float* __restrict__ gb, float* __restrict__ s1, int total) {
    int i = blockIdx.x * blockDim.x + threadIdx.x;
    if (i >= total) return;
    s1[i] = xn0[i] + 0.25f * agg[i] + gb[i & 127];
}

// ===================== launch =====================
extern "C" void kernel_launch(void* const* d_in, const int* in_sizes, int n_in,
                              void* d_out, int out_size) {
    const float* x   = (const float*)d_in[0];
    const int* ei    = (const int*)d_in[1];
    const float* ea  = (const float*)d_in[2];
    // d_in[3] = batch (unused, all zeros)
    const float* Wl  = (const float*)d_in[4];
    const float* bl  = (const float*)d_in[5];
    const float* Wr  = (const float*)d_in[6];
    const float* br  = (const float*)d_in[7];
    const float* We  = (const float*)d_in[8];
    const float* att = (const float*)d_in[9];
    const float* gb  = (const float*)d_in[10];
    const float* W1  = (const float*)d_in[11];
    const float* b1  = (const float*)d_in[12];
    const float* W2  = (const float*)d_in[13];
    const float* b2  = (const float*)d_in[14];
    const float* Wc  = (const float*)d_in[15];
    const float* bc  = (const float*)d_in[16];
    const float* nw0 = (const float*)d_in[17];
    const float* nb0 = (const float*)d_in[18];
    const float* nw1 = (const float*)d_in[19];
    const float* nb1 = (const float*)d_in[20];
    const float* nw2 = (const float*)d_in[21];
    const float* nb2 = (const float*)d_in[22];
    const float* nw3 = (const float*)d_in[23];
    const float* nb3 = (const float*)d_in[24];

    const int N = in_sizes[0] / DIM;
    const int E = in_sizes[1] / 2;
    const int ET = E + N;
    const int* esrc = ei;
    const int* edst = ei + E;

    float *p_xn0, *p_xl, *p_xr, *p_eam, *p_deg, *p_den, *p_sc, *p_agg;
    float *p_s1, *p_s2, *p_s3, *p_s4, *p_h1, *p_oc;
    unsigned* p_smax;
    double* p_st;
    cudaGetSymbolAddress((void**)&p_xn0, g_xn0);
    cudaGetSymbolAddress((void**)&p_xl, g_xl);
    cudaGetSymbolAddress((void**)&p_xr, g_xr);
    cudaGetSymbolAddress((void**)&p_eam, g_eam);
    cudaGetSymbolAddress((void**)&p_deg, g_deg);
    cudaGetSymbolAddress((void**)&p_smax, g_smax);
    cudaGetSymbolAddress((void**)&p_den, g_den);
    cudaGetSymbolAddress((void**)&p_sc, g_sc);
    cudaGetSymbolAddress((void**)&p_agg, g_agg);
    cudaGetSymbolAddress((void**)&p_s1, g_s1);
    cudaGetSymbolAddress((void**)&p_s2, g_s2);
    cudaGetSymbolAddress((void**)&p_s3, g_s3);
    cudaGetSymbolAddress((void**)&p_s4, g_s4);
    cudaGetSymbolAddress((void**)&p_h1, g_h1);
    cudaGetSymbolAddress((void**)&p_oc, g_oc);
    cudaGetSymbolAddress((void**)&p_st, g_stats);

    cudaFuncSetAttribute(score_warp_kernel, cudaFuncAttributeMaxDynamicSharedMemorySize, SC_SMEM);

    // zero scratch
    cudaMemsetAsync(p_st, 0, 8 * sizeof(double));
    cudaMemsetAsync(p_deg, 0, (size_t)N * sizeof(float));
    cudaMemsetAsync(p_eam, 0, (size_t)N * DE * sizeof(float));
    cudaMemsetAsync(p_den, 0, (size_t)N * HEADS * sizeof(float));
    cudaMemsetAsync(p_agg, 0, (size_t)N * DIM * sizeof(float));
    init_smax_kernel<<<(N * HEADS + 255) / 256, 256>>>(p_smax, N * HEADS);

    // norm0
    stats_kernel<<<1024, 256>>>(x, p_st + 0, N * DIM);
    norm_apply_kernel<<<(N * DIM + 255) / 256, 256>>>(x, p_xn0, nw0, nb0, p_st + 0, N * DIM, DIM);

    // x_l / x_r  (TF32 tensor cores)
    {
        dim3 grid(HD / 128, N / 128);
        gemm_tf32_kernel<false, false><<<grid, 256>>>(p_xn0, Wl, bl, nullptr, p_xl, N, HD, DIM);
        gemm_tf32_kernel<false, false><<<grid, 256>>>(p_xn0, Wr, br, nullptr, p_xr, N, HD, DIM);
    }

    // self-loop edge attr (scatter-mean)
    degea_kernel<<<(E * 8 + 255) / 256, 256>>>(edst, ea, p_eam, p_deg, E);
    eamdiv_kernel<<<(N * DE + 255) / 256, 256>>>(p_eam, p_deg, N * DE);

    // scores + segment max  (warp per edge)
    {
        int blocks = 1024;
        int nwarps_total = blocks * SC_WARPS;
        score_warp_kernel<<<blocks, 256, SC_SMEM>>>(
            p_xl, p_xr, esrc, edst, ea, p_eam, We, att, p_sc, p_smax, E, ET, nwarps_total);
    }

    // softmax
    exp_kernel<<<(ET * HEADS + 255) / 256, 256>>>(p_sc, p_smax, p_den, edst, E, ET);
    int write_alpha = (out_size >= N * DOUT + ET * HEADS) ? 1 : 0;
    alpha_kernel<<<(ET * HEADS + 255) / 256, 256>>>(
        p_sc, p_den, edst, (float*)d_out + (size_t)N * DOUT, E, ET, write_alpha);

    // aggregate (head-mixed, N x 128)
    aggregate_kernel<<<(ET * 32 + 255) / 256, 256>>>(p_xl, p_sc, esrc, edst, p_agg, E, ET);

    // residual + gat bias + head mean
    headmean_kernel<<<(N * DIM + 255) / 256, 256>>>(p_xn0, p_agg, gb, p_s1, N * DIM);

    // norm1
    stats_kernel<<<1024, 256>>>(p_s1, p_st + 2, N * DIM);
    norm_apply_kernel<<<(N * DIM + 255) / 256, 256>>>(p_s1, p_s2, nw1, nb1, p_st + 2, N * DIM, DIM);

    // MLP: relu(s2 @ W1^T + b1) @ W2^T + b2 + s2   (TF32 tensor cores)
    {
        dim3 g1(DHID / 128, N / 128);
        gemm_tf32_kernel<true, false><<<g1, 256>>>(p_s2, W1, b1, nullptr, p_h1, N, DHID, DIM);
        dim3 g2(DIM / 128, N / 128);
        gemm_tf32_kernel<false, true><<<g2, 256>>>(p_h1, W2, b2, p_s2, p_s3, N, DIM, DHID);
    }

    // norm2
    stats_kernel<<<1024, 256>>>(p_s3, p_st + 4, N * DIM);
    norm_apply_kernel<<<(N * DIM + 255) / 256, 256>>>(p_s3, p_s4, nw2, nb2, p_st + 4, N * DIM, DIM);

    // classifier (N=64 -> SIMT kernel)
    {
        dim3 g(DOUT / 64, N / 128);
        gemm_kernel<false, false><<<g, 256>>>(p_s4, Wc, bc, nullptr, p_oc, N, DOUT, DIM);
    }

    // norm3 -> output
    stats_kernel<<<1024, 256>>>(p_oc, p_st + 6, N * DOUT);
    norm_apply_kernel<<<(N * DOUT + 255) / 256, 256>>>(p_oc, (float*)d_out, nw3, nb3,
                                                       p_st + 6, N * DOUT, DOUT);
}

// round 8
// speedup vs baseline: 2.6066x; 1.3085x over previous
#include <cuda_runtime.h>
#include <cstdint>

// ===================== problem constants =====================
#define DIM    128      // D
#define HEADS  4        // H
#define DE     32       // edge feature dim
#define HD     512      // H*D
#define DHID   2048
#define DOUT   64
#define NMAX   16384
#define EMAX   131072
#define ETMAX  (EMAX + NMAX)
#define EPSN   1e-5f
#define SLOPE  0.2f

// ===================== scratch (static device globals; no allocs) ==========
__device__ float    g_xn0[NMAX * DIM];
__device__ float    g_xl[NMAX * HD];
__device__ float    g_xr[NMAX * HD];
__device__ float    g_eam[NMAX * DE];
__device__ float    g_deg[NMAX];
__device__ unsigned g_smax[NMAX * HEADS];
__device__ float    g_den[NMAX * HEADS];
__device__ float    g_sc[ETMAX * HEADS];
__device__ float    g_agg[NMAX * DIM];     // head-mixed: N x 128
__device__ float    g_s1[NMAX * DIM];
__device__ float    g_s2[NMAX * DIM];
__device__ float    g_s3[NMAX * DIM];
__device__ float    g_s4[NMAX * DIM];
__device__ float    g_h1[NMAX * DHID];
__device__ float    g_oc[NMAX * DOUT];
__device__ double   g_stats[8];

// ===================== helpers =====================
__device__ __forceinline__ unsigned fenc(float f) {
    unsigned u = __float_as_uint(f);
    return u ^ ((u >> 31) ? 0xFFFFFFFFu : 0x80000000u);
}
__device__ __forceinline__ float fdec(unsigned u) {
    unsigned v = u ^ ((u >> 31) ? 0x80000000u : 0xFFFFFFFFu);
    return __uint_as_float(v);
}
__device__ __forceinline__ float tf32r(float x) {
    uint32_t r;
    asm("cvt.rna.tf32.f32 %0, %1;" : "=r"(r) : "f"(x));
    return __uint_as_float(r);
}

// ===================== norm stats: sum & sumsq in fp64 =====================
__global__ void stats_kernel(const float* __restrict__ x, double* __restrict__ st, int n) {
    double s = 0.0, s2 = 0.0;
    for (int i = blockIdx.x * blockDim.x + threadIdx.x; i < n; i += gridDim.x * blockDim.x) {
        float v = x[i];
        s += (double)v;
        s2 += (double)v * (double)v;
    }
    __shared__ double sh[256], sh2[256];
    int tid = threadIdx.x;
    sh[tid] = s; sh2[tid] = s2;
    __syncthreads();
    for (int o = 128; o > 0; o >>= 1) {
        if (tid < o) { sh[tid] += sh[tid + o]; sh2[tid] += sh2[tid + o]; }
        __syncthreads();
    }
    if (tid == 0) {
        atomicAdd(&st[0], sh[0]);
        atomicAdd(&st[1], sh2[0]);
    }
}

__global__ void norm_apply_kernel(const float* __restrict__ x, float* __restrict__ y,
                                  const float* __restrict__ w, const float* __restrict__ b,
                                  const double* __restrict__ st, int n, int C) {
    int i = blockIdx.x * blockDim.x + threadIdx.x;
    if (i >= n) return;
    double cnt = (double)n;
    double mu_d = st[0] / cnt;
    double var_d = st[1] / cnt - mu_d * mu_d;
    if (var_d < 0.0) var_d = 0.0;
    float mu = (float)mu_d;
    float inv = 1.0f / ((float)sqrt(var_d) + EPSN);
    int c = i % C;
    y[i] = (x[i] - mu) * inv * w[c] + b[c];
}

// ===================== TF32 tensor-core GEMM: C = A[M,K] * B[N,K]^T + bias ==
template <bool RELU, bool RES>
__global__ __launch_bounds__(256, 2)
void gemm_tf32_kernel(const float* __restrict__ A, const float* __restrict__ B,
                      const float* __restrict__ bias, const float* __restrict__ res,
                      float* __restrict__ C, int M, int N, int K) {
    constexpr int BM = 128, BN = 128, BK = 32, LDS_ = 36;
    __shared__ float As[BM * LDS_];
    __shared__ float Bs[BN * LDS_];
    int tid = threadIdx.x;
    int wid = tid >> 5, lane = tid & 31;
    int warp_m = wid & 1;
    int warp_n = wid >> 1;
    int bm = blockIdx.y * BM, bn = blockIdx.x * BN;
    int lq = lane >> 2;
    int lr = lane & 3;

    float acc[4][4][4];
    #pragma unroll
    for (int mi = 0; mi < 4; mi++)
        #pragma unroll
        for (int ni = 0; ni < 4; ni++)
            #pragma unroll
            for (int r = 0; r < 4; r++) acc[mi][ni][r] = 0.f;

    for (int k0 = 0; k0 < K; k0 += BK) {
        #pragma unroll
        for (int it = 0; it < 4; it++) {
            int idx = it * 256 + tid;
            int r = idx >> 3, c = (idx & 7) << 2;
            float4 v = *(const float4*)(A + (size_t)(bm + r) * K + k0 + c);
            float4 t = make_float4(tf32r(v.x), tf32r(v.y), tf32r(v.z), tf32r(v.w));
            *(float4*)&As[r * LDS_ + c] = t;
        }
        #pragma unroll
        for (int it = 0; it < 4; it++) {
            int idx = it * 256 + tid;
            int r = idx >> 3, c = (idx & 7) << 2;
            float4 v = *(const float4*)(B + (size_t)(bn + r) * K + k0 + c);
            float4 t = make_float4(tf32r(v.x), tf32r(v.y), tf32r(v.z), tf32r(v.w));
            *(float4*)&Bs[r * LDS_ + c] = t;
        }
        __syncthreads();

        #pragma unroll
        for (int kk = 0; kk < BK; kk += 8) {
            uint32_t a[4][4], b[4][2];
            #pragma unroll
            for (int mi = 0; mi < 4; mi++) {
                int row = warp_m * 64 + mi * 16 + lq;
                a[mi][0] = __float_as_uint(As[row * LDS_ + kk + lr]);
                a[mi][1] = __float_as_uint(As[(row + 8) * LDS_ + kk + lr]);
                a[mi][2] = __float_as_uint(As[row * LDS_ + kk + lr + 4]);
                a[mi][3] = __float_as_uint(As[(row + 8) * LDS_ + kk + lr + 4]);
            }
            #pragma unroll
            for (int ni = 0; ni < 4; ni++) {
                int col = warp_n * 32 + ni * 8 + lq;
                b[ni][0] = __float_as_uint(Bs[col * LDS_ + kk + lr]);
                b[ni][1] = __float_as_uint(Bs[col * LDS_ + kk + lr + 4]);
            }
            #pragma unroll
            for (int mi = 0; mi < 4; mi++)
                #pragma unroll
                for (int ni = 0; ni < 4; ni++) {
                    asm volatile(
                        "mma.sync.aligned.m16n8k8.row.col.f32.tf32.tf32.f32 "
                        "{%0,%1,%2,%3}, {%4,%5,%6,%7}, {%8,%9}, {%0,%1,%2,%3};"
                        : "+f"(acc[mi][ni][0]), "+f"(acc[mi][ni][1]),
                          "+f"(acc[mi][ni][2]), "+f"(acc[mi][ni][3])
                        : "r"(a[mi][0]), "r"(a[mi][1]), "r"(a[mi][2]), "r"(a[mi][3]),
                          "r"(b[ni][0]), "r"(b[ni][1]));
                }
        }
        __syncthreads();
    }

    #pragma unroll
    for (int mi = 0; mi < 4; mi++) {
        int row = bm + warp_m * 64 + mi * 16 + lq;
        #pragma unroll
        for (int ni = 0; ni < 4; ni++) {
            int col = bn + warp_n * 32 + ni * 8 + (lr << 1);
            float b0 = bias[col], b1 = bias[col + 1];
            #pragma unroll
            for (int h = 0; h < 2; h++) {
                int rr = row + h * 8;
                float v0 = acc[mi][ni][h * 2 + 0] + b0;
                float v1 = acc[mi][ni][h * 2 + 1] + b1;
                if (RELU) { v0 = fmaxf(v0, 0.f); v1 = fmaxf(v1, 0.f); }
                size_t o = (size_t)rr * N + col;
                if (RES) { v0 += res[o]; v1 += res[o + 1]; }
                *(float2*)(C + o) = make_float2(v0, v1);
            }
        }
    }
}

// ===================== SIMT SGEMM (small N: classifier) =====================
template <bool RELU, bool RES>
__global__ void gemm_kernel(const float* __restrict__ A, const float* __restrict__ B,
                            const float* __restrict__ bias, const float* __restrict__ res,
                            float* __restrict__ C, int M, int N, int K) {
    constexpr int BM = 128, BN = 64, BK = 16, TM = 8, TN = 4, THREADS = 256;
    __shared__ float As[BK][BM];
    __shared__ float Bs[BK][BN];
    int tid = threadIdx.x;
    int bm = blockIdx.y * BM, bn = blockIdx.x * BN;
    int tcol = tid & 15;
    int trow = tid >> 4;
    float acc[TM][TN];
    #pragma unroll
    for (int i = 0; i < TM; i++)
        #pragma unroll
        for (int j = 0; j < TN; j++) acc[i][j] = 0.f;

    for (int k0 = 0; k0 < K; k0 += BK) {
        #pragma unroll
        for (int i = tid; i < BM * BK / 4; i += THREADS) {
            int r = i >> 2;
            int c = (i & 3) << 2;
            float4 v = *(const float4*)(A + (size_t)(bm + r) * K + k0 + c);
            As[c + 0][r] = v.x; As[c + 1][r] = v.y; As[c + 2][r] = v.z; As[c + 3][r] = v.w;
        }
        #pragma unroll
        for (int i = tid; i < BN * BK / 4; i += THREADS) {
            int r = i >> 2;
            int c = (i & 3) << 2;
            float4 v = *(const float4*)(B + (size_t)(bn + r) * K + k0 + c);
            Bs[c + 0][r] = v.x; Bs[c + 1][r] = v.y; Bs[c + 2][r] = v.z; Bs[c + 3][r] = v.w;
        }
        __syncthreads();
        #pragma unroll
        for (int k = 0; k < BK; k++) {
            float4 a0 = *(const float4*)&As[k][trow * TM];
            float4 a1 = *(const float4*)&As[k][trow * TM + 4];
            float4 b0 = *(const float4*)&Bs[k][tcol * TN];
            float av[TM] = {a0.x, a0.y, a0.z, a0.w, a1.x, a1.y, a1.z, a1.w};
            float bv[TN] = {b0.x, b0.y, b0.z, b0.w};
            #pragma unroll
            for (int i = 0; i < TM; i++)
                #pragma unroll
                for (int j = 0; j < TN; j++) acc[i][j] += av[i] * bv[j];
        }
        __syncthreads();
    }
    int row0 = bm + trow * TM;
    int col0 = bn + tcol * TN;
    #pragma unroll
    for (int i = 0; i < TM; i++) {
        size_t base = (size_t)(row0 + i) * N + col0;
        #pragma unroll
        for (int j = 0; j < TN; j++) {
            float v = acc[i][j] + bias[col0 + j];
            if (RELU) v = v > 0.f ? v : 0.f;
            if (RES) v += res[base + j];
            C[base + j] = v;
        }
    }
}

// ===================== GAT edge kernels =====================
// vectorized scatter-mean accumulation: one thread per (edge, k4)
__global__ void degea_kernel(const int* __restrict__ edst, const float* __restrict__ ea,
                             float* __restrict__ eam, float* __restrict__ deg, int E) {
    int i = blockIdx.x * blockDim.x + threadIdx.x;
    if (i >= E * 8) return;
    int e = i >> 3, k4 = i & 7;
    int d = __ldg(edst + e);
    float4 v = *(const float4*)(ea + (size_t)e * DE + k4 * 4);
    float* p = eam + (size_t)d * DE + k4 * 4;
    asm volatile("red.global.add.v4.f32 [%0], {%1,%2,%3,%4};"
                 :: "l"(p), "f"(v.x), "f"(v.y), "f"(v.z), "f"(v.w) : "memory");
    if (k4 == 0) {
        float* q = deg + d;
        asm volatile("red.global.add.f32 [%0], %1;" :: "l"(q), "f"(1.0f) : "memory");
    }
}

__global__ void eamdiv_kernel(float* __restrict__ eam, const float* __restrict__ deg, int n32) {
    int i = blockIdx.x * blockDim.x + threadIdx.x;
    if (i >= n32) return;
    eam[i] *= 1.f / fmaxf(deg[i >> 5], 1.f);
}

__global__ void init_smax_kernel(unsigned* __restrict__ smax, int n) {
    int i = blockIdx.x * blockDim.x + threadIdx.x;
    if (i < n) smax[i] = 0x007FFFFFu;  // fenc(-inf)
}

// ===================== MMA-based score kernel =====================
// Per 16-edge tile: EF[16,512] = ea[16,32] @ We[512,32]^T via tf32 MMA (smem),
// then warp-per-edge: score_h = att_h . lrelu(xl[src]+xr[dst]+EF)
#define SC_TE   16
#define SC_EFP  520
#define SC_SMEM ((512 * 36 + 512 + SC_TE * 36 + SC_TE * SC_EFP) * 4)
__global__ __launch_bounds__(256)
void score_mma_kernel(const float* __restrict__ XL, const float* __restrict__ XR,
                      const int* __restrict__ esrc, const int* __restrict__ edst,
                      const float* __restrict__ eattr, const float* __restrict__ eam,
                      const float* __restrict__ We, const float* __restrict__ att,
                      float* __restrict__ SC, unsigned* __restrict__ SMAX,
                      int E, int ET) {
    extern __shared__ float sm[];
    float* We_s = sm;                           // 512 x 36 (tf32)
    float* att_s = We_s + 512 * 36;             // 512
    float* As   = att_s + 512;                  // 16 x 36 (ea tile, tf32)
    float* EF   = As + SC_TE * 36;              // 16 x 520
    __shared__ int src_s[SC_TE], dst_s[SC_TE];
    int tid = threadIdx.x;
    int wid = tid >> 5, lane = tid & 31;
    int lq = lane >> 2, lr = lane & 3;

    // preload We (tf32) + att
    for (int i = tid; i < 512 * 8; i += 256) {
        int r = i >> 3, c = (i & 7) << 2;
        float4 v = *(const float4*)(We + (size_t)r * DE + c);
        float4 t = make_float4(tf32r(v.x), tf32r(v.y), tf32r(v.z), tf32r(v.w));
        *(float4*)&We_s[r * 36 + c] = t;
    }
    for (int i = tid; i < 512; i += 256) att_s[i] = att[i];
    __syncthreads();

    for (int base = blockIdx.x * SC_TE; base < ET; base += gridDim.x * SC_TE) {
        // load edge meta + ea tile
        if (tid < SC_TE) {
            int e = base + tid;
            int s = 0, d = 0;
            if (e < ET) {
                if (e < E) { s = __ldg(esrc + e); d = __ldg(edst + e); }
                else       { s = d = e - E; }
            }
            src_s[tid] = s; dst_s[tid] = d;
        }
        for (int i = tid; i < SC_TE * DE; i += 256) {
            int el = i >> 5, k = i & 31;
            int e = base + el;
            float v = 0.f;
            if (e < ET) v = (e < E) ? __ldg(eattr + (size_t)e * DE + k)
                                    : __ldg(eam + (size_t)(e - E) * DE + k);
            As[el * 36 + k] = tf32r(v);
        }
        __syncthreads();

        // MMA phase: warp wid handles idx range [wid*64, wid*64+64)
        {
            float c[8][4];
            #pragma unroll
            for (int nt = 0; nt < 8; nt++)
                #pragma unroll
                for (int r = 0; r < 4; r++) c[nt][r] = 0.f;
            #pragma unroll
            for (int kk = 0; kk < 32; kk += 8) {
                uint32_t a0 = __float_as_uint(As[lq * 36 + kk + lr]);
                uint32_t a1 = __float_as_uint(As[(lq + 8) * 36 + kk + lr]);
                uint32_t a2 = __float_as_uint(As[lq * 36 + kk + lr + 4]);
                uint32_t a3 = __float_as_uint(As[(lq + 8) * 36 + kk + lr + 4]);
                #pragma unroll
                for (int nt = 0; nt < 8; nt++) {
                    int col = wid * 64 + nt * 8 + lq;
                    uint32_t b0 = __float_as_uint(We_s[col * 36 + kk + lr]);
                    uint32_t b1 = __float_as_uint(We_s[col * 36 + kk + lr + 4]);
                    asm volatile(
                        "mma.sync.aligned.m16n8k8.row.col.f32.tf32.tf32.f32 "
                        "{%0,%1,%2,%3}, {%4,%5,%6,%7}, {%8,%9}, {%0,%1,%2,%3};"
                        : "+f"(c[nt][0]), "+f"(c[nt][1]), "+f"(c[nt][2]), "+f"(c[nt][3])
                        : "r"(a0), "r"(a1), "r"(a2), "r"(a3), "r"(b0), "r"(b1));
                }
            }
            #pragma unroll
            for (int nt = 0; nt < 8; nt++) {
                int col0 = wid * 64 + nt * 8 + lr * 2;
                EF[lq * SC_EFP + col0]           = c[nt][0];
                EF[lq * SC_EFP + col0 + 1]       = c[nt][1];
                EF[(lq + 8) * SC_EFP + col0]     = c[nt][2];
                EF[(lq + 8) * SC_EFP + col0 + 1] = c[nt][3];
            }
        }
        __syncthreads();

        // score phase: warp wid handles edges base+wid*2, base+wid*2+1
        #pragma unroll
        for (int sub = 0; sub < 2; sub++) {
            int el = wid * 2 + sub;
            int e = base + el;
            if (e >= ET) break;
            int s = src_s[el], d = dst_s[el];
            const float* xlp = XL + (size_t)s * HD;
            const float* xrp = XR + (size_t)d * HD;
            const float* efp = EF + el * SC_EFP;
            float ah[4] = {0.f, 0.f, 0.f, 0.f};
            #pragma unroll
            for (int j = 0; j < 16; j++) {
                int idx = lane + 32 * j;
                float v = __ldg(xlp + idx) + __ldg(xrp + idx) + efp[idx];
                v = v > 0.f ? v : SLOPE * v;
                ah[j >> 2] += v * att_s[idx];
            }
            #pragma unroll
            for (int h = 0; h < 4; h++) {
                float v = ah[h];
                #pragma unroll
                for (int o = 16; o > 0; o >>= 1) v += __shfl_down_sync(0xFFFFFFFFu, v, o);
                if (lane == 0) {
                    SC[(size_t)e * HEADS + h] = v;
                    atomicMax(&SMAX[(size_t)d * HEADS + h], fenc(v));
                }
            }
        }
        __syncthreads();
    }
}

__global__ void exp_kernel(float* __restrict__ SC, const unsigned* __restrict__ SMAX,
                           float* __restrict__ den, const int* __restrict__ edst,
                           int E, int ET) {
    int i = blockIdx.x * blockDim.x + threadIdx.x;
    if (i >= ET * HEADS) return;
    int e = i >> 2, h = i & 3;
    int d = (e < E) ? __ldg(edst + e) : (e - E);
    float m = fdec(SMAX[d * HEADS + h]);
    float ex = expf(SC[i] - m);
    SC[i] = ex;
    atomicAdd(&den[d * HEADS + h], ex);
}

__global__ void alpha_kernel(float* __restrict__ SC, const float* __restrict__ den,
                             const int* __restrict__ edst, float* __restrict__ out_alpha,
                             int E, int ET, int write_out) {
    int i = blockIdx.x * blockDim.x + threadIdx.x;
    if (i >= ET * HEADS) return;
    int e = i >> 2, h = i & 3;
    int d = (e < E) ? __ldg(edst + e) : (e - E);
    float a = SC[i] / den[d * HEADS + h];
    SC[i] = a;
    if (write_out) out_alpha[i] = a;
}

// one warp per edge, head-mixed: AGG[dst,c] += sum_h alpha_h * XL[src, h*128+c]
__global__ void aggregate_kernel(const float* __restrict__ XL, const float* __restrict__ SC,
                                 const int* __restrict__ esrc, const int* __restrict__ edst,
                                 float* __restrict__ AGG, int E, int ET) {
    int warp = (blockIdx.x * blockDim.x + threadIdx.x) >> 5;
    int lane = threadIdx.x & 31;
    if (warp >= ET) return;
    int e = warp;
    int s = (e < E) ? __ldg(esrc + e) : (e - E);
    int d = (e < E) ? __ldg(edst + e) : (e - E);
    float4 al = *(const float4*)(SC + (size_t)e * HEADS);
    const float4* xl4 = (const float4*)(XL + (size_t)s * HD);
    float4 v0 = __ldg(xl4 + 0 * 32 + lane);
    float4 v1 = __ldg(xl4 + 1 * 32 + lane);
    float4 v2 = __ldg(xl4 + 2 * 32 + lane);
    float4 v3 = __ldg(xl4 + 3 * 32 + lane);
    float rx = al.x * v0.x + al.y * v1.x + al.z * v2.x + al.w * v3.x;
    float ry = al.x * v0.y + al.y * v1.y + al.z * v2.y + al.w * v3.y;
    float rz = al.x * v0.z + al.y * v1.z + al.z * v2.z + al.w * v3.z;
    float rw = al.x * v0.w + al.y * v1.w + al.z * v2.w + al.w * v3.w;
    float* p = AGG + (size_t)d * DIM + lane * 4;
    asm volatile("red.global.add.v4.f32 [%0], {%1,%2,%3,%4};"
                 :: "l"(p), "f"(rx), "f"(ry), "f"(rz), "f"(rw) : "memory");
}

__global__ void headmean_kernel(const float* __restrict__ xn0, const float* __restrict__ agg,
                                const float* __restrict__ gb, float* __restrict__ s1, int total) {
    int i = blockIdx.x * blockDim.x + threadIdx.x;
    if (i >= total) return;
    s1[i] = xn0[i] + 0.25f * agg[i] + gb[i & 127];
}

// ===================== launch =====================
extern "C" void kernel_launch(void* const* d_in, const int* in_sizes, int n_in,
                              void* d_out, int out_size) {
    const float* x   = (const float*)d_in[0];
    const int* ei    = (const int*)d_in[1];
    const float* ea  = (const float*)d_in[2];
    // d_in[3] = batch (unused, all zeros)
    const float* Wl  = (const float*)d_in[4];
    const float* bl  = (const float*)d_in[5];
    const float* Wr  = (const float*)d_in[6];
    const float* br  = (const float*)d_in[7];
    const float* We  = (const float*)d_in[8];
    const float* att = (const float*)d_in[9];
    const float* gb  = (const float*)d_in[10];
    const float* W1  = (const float*)d_in[11];
    const float* b1  = (const float*)d_in[12];
    const float* W2  = (const float*)d_in[13];
    const float* b2  = (const float*)d_in[14];
    const float* Wc  = (const float*)d_in[15];
    const float* bc  = (const float*)d_in[16];
    const float* nw0 = (const float*)d_in[17];
    const float* nb0 = (const float*)d_in[18];
    const float* nw1 = (const float*)d_in[19];
    const float* nb1 = (const float*)d_in[20];
    const float* nw2 = (const float*)d_in[21];
    const float* nb2 = (const float*)d_in[22];
    const float* nw3 = (const float*)d_in[23];
    const float* nb3 = (const float*)d_in[24];

    const int N = in_sizes[0] / DIM;
    const int E = in_sizes[1] / 2;
    const int ET = E + N;
    const int* esrc = ei;
    const int* edst = ei + E;

    float *p_xn0, *p_xl, *p_xr, *p_eam, *p_deg, *p_den, *p_sc, *p_agg;
    float *p_s1, *p_s2, *p_s3, *p_s4, *p_h1, *p_oc;
    unsigned* p_smax;
    double* p_st;
    cudaGetSymbolAddress((void**)&p_xn0, g_xn0);
    cudaGetSymbolAddress((void**)&p_xl, g_xl);
    cudaGetSymbolAddress((void**)&p_xr, g_xr);
    cudaGetSymbolAddress((void**)&p_eam, g_eam);
    cudaGetSymbolAddress((void**)&p_deg, g_deg);
    cudaGetSymbolAddress((void**)&p_smax, g_smax);
    cudaGetSymbolAddress((void**)&p_den, g_den);
    cudaGetSymbolAddress((void**)&p_sc, g_sc);
    cudaGetSymbolAddress((void**)&p_agg, g_agg);
    cudaGetSymbolAddress((void**)&p_s1, g_s1);
    cudaGetSymbolAddress((void**)&p_s2, g_s2);
    cudaGetSymbolAddress((void**)&p_s3, g_s3);
    cudaGetSymbolAddress((void**)&p_s4, g_s4);
    cudaGetSymbolAddress((void**)&p_h1, g_h1);
    cudaGetSymbolAddress((void**)&p_oc, g_oc);
    cudaGetSymbolAddress((void**)&p_st, g_stats);

    cudaFuncSetAttribute(score_mma_kernel, cudaFuncAttributeMaxDynamicSharedMemorySize, SC_SMEM);

    // zero scratch
    cudaMemsetAsync(p_st, 0, 8 * sizeof(double));
    cudaMemsetAsync(p_deg, 0, (size_t)N * sizeof(float));
    cudaMemsetAsync(p_eam, 0, (size_t)N * DE * sizeof(float));
    cudaMemsetAsync(p_den, 0, (size_t)N * HEADS * sizeof(float));
    cudaMemsetAsync(p_agg, 0, (size_t)N * DIM * sizeof(float));
    init_smax_kernel<<<(N * HEADS + 255) / 256, 256>>>(p_smax, N * HEADS);

    // norm0
    stats_kernel<<<1024, 256>>>(x, p_st + 0, N * DIM);
    norm_apply_kernel<<<(N * DIM + 255) / 256, 256>>>(x, p_xn0, nw0, nb0, p_st + 0, N * DIM, DIM);

    // x_l / x_r  (TF32 tensor cores)
    {
        dim3 grid(HD / 128, N / 128);
        gemm_tf32_kernel<false, false><<<grid, 256>>>(p_xn0, Wl, bl, nullptr, p_xl, N, HD, DIM);
        gemm_tf32_kernel<false, false><<<grid, 256>>>(p_xn0, Wr, br, nullptr, p_xr, N, HD, DIM);
    }

    // self-loop edge attr (scatter-mean)
    degea_kernel<<<(E * 8 + 255) / 256, 256>>>(edst, ea, p_eam, p_deg, E);
    eamdiv_kernel<<<(N * DE + 255) / 256, 256>>>(p_eam, p_deg, N * DE);

    // scores + segment max  (MMA e_feat + warp-per-edge)
    score_mma_kernel<<<1024, 256, SC_SMEM>>>(
        p_xl, p_xr, esrc, edst, ea, p_eam, We, att, p_sc, p_smax, E, ET);

    // softmax
    exp_kernel<<<(ET * HEADS + 255) / 256, 256>>>(p_sc, p_smax, p_den, edst, E, ET);
    int write_alpha = (out_size >= N * DOUT + ET * HEADS) ? 1 : 0;
    alpha_kernel<<<(ET * HEADS + 255) / 256, 256>>>(
        p_sc, p_den, edst, (float*)d_out + (size_t)N * DOUT, E, ET, write_alpha);

    // aggregate (head-mixed, N x 128)
    aggregate_kernel<<<(ET * 32 + 255) / 256, 256>>>(p_xl, p_sc, esrc, edst, p_agg, E, ET);

    // residual + gat bias + head mean
    headmean_kernel<<<(N * DIM + 255) / 256, 256>>>(p_xn0, p_agg, gb, p_s1, N * DIM);

    // norm1
    stats_kernel<<<1024, 256>>>(p_s1, p_st + 2, N * DIM);
    norm_apply_kernel<<<(N * DIM + 255) / 256, 256>>>(p_s1, p_s2, nw1, nb1, p_st + 2, N * DIM, DIM);

    // MLP: relu(s2 @ W1^T + b1) @ W2^T + b2 + s2   (TF32 tensor cores)
    {
        dim3 g1(DHID / 128, N / 128);
        gemm_tf32_kernel<true, false><<<g1, 256>>>(p_s2, W1, b1, nullptr, p_h1, N, DHID, DIM);
        dim3 g2(DIM / 128, N / 128);
        gemm_tf32_kernel<false, true><<<g2, 256>>>(p_h1, W2, b2, p_s2, p_s3, N, DIM, DHID);
    }

    // norm2
    stats_kernel<<<1024, 256>>>(p_s3, p_st + 4, N * DIM);
    norm_apply_kernel<<<(N * DIM + 255) / 256, 256>>>(p_s3, p_s4, nw2, nb2, p_st + 4, N * DIM, DIM);

    // classifier (N=64 -> SIMT kernel)
    {
        dim3 g(DOUT / 64, N / 128);
        gemm_kernel<false, false><<<g, 256>>>(p_s4, Wc, bc, nullptr, p_oc, N, DOUT, DIM);
    }

    // norm3 -> output
    stats_kernel<<<1024, 256>>>(p_oc, p_st + 6, N * DOUT);
    norm_apply_kernel<<<(N * DOUT + 255) / 256, 256>>>(p_oc, (float*)d_out, nw3, nb3,
                                                       p_st + 6, N * DOUT, DOUT);
}

// round 10
// speedup vs baseline: 2.8017x; 1.0749x over previous
#include <cuda_runtime.h>
#include <cstdint>

// ===================== problem constants =====================
#define DIM    128      // D
#define HEADS  4        // H
#define DE     32       // edge feature dim
#define HD     512      // H*D
#define DHID   2048
#define DOUT   64
#define NMAX   16384
#define EMAX   131072
#define ETMAX  (EMAX + NMAX)
#define EPSN   1e-5f
#define SLOPE  0.2f

// ===================== scratch (static device globals; no allocs) ==========
__device__ float    g_xn0[NMAX * DIM];
__device__ float    g_xl[NMAX * HD];
__device__ float    g_xr[NMAX * HD];
__device__ float    g_eam[NMAX * DE];
__device__ float    g_deg[NMAX];
__device__ unsigned g_smax[NMAX * HEADS];
__device__ float    g_den[NMAX * HEADS];
__device__ float    g_sc[ETMAX * HEADS];
__device__ float    g_agg[NMAX * DIM];     // head-mixed: N x 128
__device__ float    g_s1[NMAX * DIM];
__device__ float    g_s2[NMAX * DIM];
__device__ float    g_s3[NMAX * DIM];
__device__ float    g_s4[NMAX * DIM];
__device__ float    g_h1[NMAX * DHID];
__device__ float    g_oc[NMAX * DOUT];
__device__ double   g_stats[8];

// ===================== helpers =====================
__device__ __forceinline__ unsigned fenc(float f) {
    unsigned u = __float_as_uint(f);
    return u ^ ((u >> 31) ? 0xFFFFFFFFu : 0x80000000u);
}
__device__ __forceinline__ float fdec(unsigned u) {
    unsigned v = u ^ ((u >> 31) ? 0x80000000u : 0xFFFFFFFFu);
    return __uint_as_float(v);
}
__device__ __forceinline__ float tf32r(float x) {
    uint32_t r;
    asm("cvt.rna.tf32.f32 %0, %1;" : "=r"(r) : "f"(x));
    return __uint_as_float(r);
}

// ===================== norm stats: sum & sumsq in fp64 =====================
__global__ void stats_kernel(const float* __restrict__ x, double* __restrict__ st, int n) {
    double s = 0.0, s2 = 0.0;
    for (int i = blockIdx.x * blockDim.x + threadIdx.x; i < n; i += gridDim.x * blockDim.x) {
        float v = x[i];
        s += (double)v;
        s2 += (double)v * (double)v;
    }
    __shared__ double sh[256], sh2[256];
    int tid = threadIdx.x;
    sh[tid] = s; sh2[tid] = s2;
    __syncthreads();
    for (int o = 128; o > 0; o >>= 1) {
        if (tid < o) { sh[tid] += sh[tid + o]; sh2[tid] += sh2[tid + o]; }
        __syncthreads();
    }
    if (tid == 0) {
        atomicAdd(&st[0], sh[0]);
        atomicAdd(&st[1], sh2[0]);
    }
}

__global__ void norm_apply_kernel(const float* __restrict__ x, float* __restrict__ y,
                                  const float* __restrict__ w, const float* __restrict__ b,
                                  const double* __restrict__ st, int n, int C) {
    int i = blockIdx.x * blockDim.x + threadIdx.x;
    if (i >= n) return;
    double cnt = (double)n;
    double mu_d = st[0] / cnt;
    double var_d = st[1] / cnt - mu_d * mu_d;
    if (var_d < 0.0) var_d = 0.0;
    float mu = (float)mu_d;
    float inv = 1.0f / ((float)sqrt(var_d) + EPSN);
    int c = i % C;
    y[i] = (x[i] - mu) * inv * w[c] + b[c];
}

// ===================== TF32 tensor-core GEMM: C = A[M,K] * B[N,K]^T + bias ==
template <bool RELU, bool RES>
__global__ __launch_bounds__(256, 2)
void gemm_tf32_kernel(const float* __restrict__ A, const float* __restrict__ B,
                      const float* __restrict__ bias, const float* __restrict__ res,
                      float* __restrict__ C, int M, int N, int K) {
    constexpr int BM = 128, BN = 128, BK = 32, LDS_ = 36;
    __shared__ float As[BM * LDS_];
    __shared__ float Bs[BN * LDS_];
    int tid = threadIdx.x;
    int wid = tid >> 5, lane = tid & 31;
    int warp_m = wid & 1;
    int warp_n = wid >> 1;
    int bm = blockIdx.y * BM, bn = blockIdx.x * BN;
    int lq = lane >> 2;
    int lr = lane & 3;

    float acc[4][4][4];
    #pragma unroll
    for (int mi = 0; mi < 4; mi++)
        #pragma unroll
        for (int ni = 0; ni < 4; ni++)
            #pragma unroll
            for (int r = 0; r < 4; r++) acc[mi][ni][r] = 0.f;

    for (int k0 = 0; k0 < K; k0 += BK) {
        #pragma unroll
        for (int it = 0; it < 4; it++) {
            int idx = it * 256 + tid;
            int r = idx >> 3, c = (idx & 7) << 2;
            float4 v = *(const float4*)(A + (size_t)(bm + r) * K + k0 + c);
            float4 t = make_float4(tf32r(v.x), tf32r(v.y), tf32r(v.z), tf32r(v.w));
            *(float4*)&As[r * LDS_ + c] = t;
        }
        #pragma unroll
        for (int it = 0; it < 4; it++) {
            int idx = it * 256 + tid;
            int r = idx >> 3, c = (idx & 7) << 2;
            float4 v = *(const float4*)(B + (size_t)(bn + r) * K + k0 + c);
            float4 t = make_float4(tf32r(v.x), tf32r(v.y), tf32r(v.z), tf32r(v.w));
            *(float4*)&Bs[r * LDS_ + c] = t;
        }
        __syncthreads();

        #pragma unroll
        for (int kk = 0; kk < BK; kk += 8) {
            uint32_t a[4][4], b[4][2];
            #pragma unroll
            for (int mi = 0; mi < 4; mi++) {
                int row = warp_m * 64 + mi * 16 + lq;
                a[mi][0] = __float_as_uint(As[row * LDS_ + kk + lr]);
                a[mi][1] = __float_as_uint(As[(row + 8) * LDS_ + kk + lr]);
                a[mi][2] = __float_as_uint(As[row * LDS_ + kk + lr + 4]);
                a[mi][3] = __float_as_uint(As[(row + 8) * LDS_ + kk + lr + 4]);
            }
            #pragma unroll
            for (int ni = 0; ni < 4; ni++) {
                int col = warp_n * 32 + ni * 8 + lq;
                b[ni][0] = __float_as_uint(Bs[col * LDS_ + kk + lr]);
                b[ni][1] = __float_as_uint(Bs[col * LDS_ + kk + lr + 4]);
            }
            #pragma unroll
            for (int mi = 0; mi < 4; mi++)
                #pragma unroll
                for (int ni = 0; ni < 4; ni++) {
                    asm volatile(
                        "mma.sync.aligned.m16n8k8.row.col.f32.tf32.tf32.f32 "
                        "{%0,%1,%2,%3}, {%4,%5,%6,%7}, {%8,%9}, {%0,%1,%2,%3};"
                        : "+f"(acc[mi][ni][0]), "+f"(acc[mi][ni][1]),
                          "+f"(acc[mi][ni][2]), "+f"(acc[mi][ni][3])
                        : "r"(a[mi][0]), "r"(a[mi][1]), "r"(a[mi][2]), "r"(a[mi][3]),
                          "r"(b[ni][0]), "r"(b[ni][1]));
                }
        }
        __syncthreads();
    }

    #pragma unroll
    for (int mi = 0; mi < 4; mi++) {
        int row = bm + warp_m * 64 + mi * 16 + lq;
        #pragma unroll
        for (int ni = 0; ni < 4; ni++) {
            int col = bn + warp_n * 32 + ni * 8 + (lr << 1);
            float b0 = bias[col], b1 = bias[col + 1];
            #pragma unroll
            for (int h = 0; h < 2; h++) {
                int rr = row + h * 8;
                float v0 = acc[mi][ni][h * 2 + 0] + b0;
                float v1 = acc[mi][ni][h * 2 + 1] + b1;
                if (RELU) { v0 = fmaxf(v0, 0.f); v1 = fmaxf(v1, 0.f); }
                size_t o = (size_t)rr * N + col;
                if (RES) { v0 += res[o]; v1 += res[o + 1]; }
                *(float2*)(C + o) = make_float2(v0, v1);
            }
        }
    }
}

// ===================== split-K TF32 GEMM: partials via red.global.add ======
// C must be pre-zeroed. z==0 slice adds bias (+ residual).
__global__ __launch_bounds__(256, 2)
void gemm_tf32_splitk_kernel(const float* __restrict__ A, const float* __restrict__ B,
                             const float* __restrict__ bias, const float* __restrict__ res,
                             float* __restrict__ C, int M, int N, int K, int Kc) {
    constexpr int BM = 128, BN = 128, BK = 32, LDS_ = 36;
    __shared__ float As[BM * LDS_];
    __shared__ float Bs[BN * LDS_];
    int tid = threadIdx.x;
    int wid = tid >> 5, lane = tid & 31;
    int warp_m = wid & 1;
    int warp_n = wid >> 1;
    int bm = blockIdx.y * BM, bn = blockIdx.x * BN;
    int kz0 = blockIdx.z * Kc;
    int kz1 = kz0 + Kc; if (kz1 > K) kz1 = K;
    int lq = lane >> 2;
    int lr = lane & 3;

    float acc[4][4][4];
    #pragma unroll
    for (int mi = 0; mi < 4; mi++)
        #pragma unroll
        for (int ni = 0; ni < 4; ni++)
            #pragma unroll
            for (int r = 0; r < 4; r++) acc[mi][ni][r] = 0.f;

    for (int k0 = kz0; k0 < kz1; k0 += BK) {
        #pragma unroll
        for (int it = 0; it < 4; it++) {
            int idx = it * 256 + tid;
            int r = idx >> 3, c = (idx & 7) << 2;
            float4 v = *(const float4*)(A + (size_t)(bm + r) * K + k0 + c);
            float4 t = make_float4(tf32r(v.x), tf32r(v.y), tf32r(v.z), tf32r(v.w));
            *(float4*)&As[r * LDS_ + c] = t;
        }
        #pragma unroll
        for (int it = 0; it < 4; it++) {
            int idx = it * 256 + tid;
            int r = idx >> 3, c = (idx & 7) << 2;
            float4 v = *(const float4*)(B + (size_t)(bn + r) * K + k0 + c);
            float4 t = make_float4(tf32r(v.x), tf32r(v.y), tf32r(v.z), tf32r(v.w));
            *(float4*)&Bs[r * LDS_ + c] = t;
        }
        __syncthreads();

        #pragma unroll
        for (int kk = 0; kk < BK; kk += 8) {
            uint32_t a[4][4], b[4][2];
            #pragma unroll
            for (int mi = 0; mi < 4; mi++) {
                int row = warp_m * 64 + mi * 16 + lq;
                a[mi][0] = __float_as_uint(As[row * LDS_ + kk + lr]);
                a[mi][1] = __float_as_uint(As[(row + 8) * LDS_ + kk + lr]);
                a[mi][2] = __float_as_uint(As[row * LDS_ + kk + lr + 4]);
                a[mi][3] = __float_as_uint(As[(row + 8) * LDS_ + kk + lr + 4]);
            }
            #pragma unroll
            for (int ni = 0; ni < 4; ni++) {
                int col = warp_n * 32 + ni * 8 + lq;
                b[ni][0] = __float_as_uint(Bs[col * LDS_ + kk + lr]);
                b[ni][1] = __float_as_uint(Bs[col * LDS_ + kk + lr + 4]);
            }
            #pragma unroll
            for (int mi = 0; mi < 4; mi++)
                #pragma unroll
                for (int ni = 0; ni < 4; ni++) {
                    asm volatile(
                        "mma.sync.aligned.m16n8k8.row.col.f32.tf32.tf32.f32 "
                        "{%0,%1,%2,%3}, {%4,%5,%6,%7}, {%8,%9}, {%0,%1,%2,%3};"
                        : "+f"(acc[mi][ni][0]), "+f"(acc[mi][ni][1]),
                          "+f"(acc[mi][ni][2]), "+f"(acc[mi][ni][3])
                        : "r"(a[mi][0]), "r"(a[mi][1]), "r"(a[mi][2]), "r"(a[mi][3]),
                          "r"(b[ni][0]), "r"(b[ni][1]));
                }
        }
        __syncthreads();
    }

    bool first = (blockIdx.z == 0);
    #pragma unroll
    for (int mi = 0; mi < 4; mi++) {
        int row = bm + warp_m * 64 + mi * 16 + lq;
        #pragma unroll
        for (int ni = 0; ni < 4; ni++) {
            int col = bn + warp_n * 32 + ni * 8 + (lr << 1);
            #pragma unroll
            for (int h = 0; h < 2; h++) {
                int rr = row + h * 8;
                float v0 = acc[mi][ni][h * 2 + 0];
                float v1 = acc[mi][ni][h * 2 + 1];
                size_t o = (size_t)rr * N + col;
                if (first) {
                    v0 += bias[col] + res[o];
                    v1 += bias[col + 1] + res[o + 1];
                }
                asm volatile("red.global.add.v2.f32 [%0], {%1,%2};"
                             :: "l"(C + o), "f"(v0), "f"(v1) : "memory");
            }
        }
    }
}

// ===================== SIMT SGEMM (small N: classifier) =====================
template <bool RELU, bool RES>
__global__ void gemm_kernel(const float* __restrict__ A, const float* __restrict__ B,
                            const float* __restrict__ bias, const float* __restrict__ res,
                            float* __restrict__ C, int M, int N, int K) {
    constexpr int BM = 128, BN = 64, BK = 16, TM = 8, TN = 4, THREADS = 256;
    __shared__ float As[BK][BM];
    __shared__ float Bs[BK][BN];
    int tid = threadIdx.x;
    int bm = blockIdx.y * BM, bn = blockIdx.x * BN;
    int tcol = tid & 15;
    int trow = tid >> 4;
    float acc[TM][TN];
    #pragma unroll
    for (int i = 0; i < TM; i++)
        #pragma unroll
        for (int j = 0; j < TN; j++) acc[i][j] = 0.f;

    for (int k0 = 0; k0 < K; k0 += BK) {
        #pragma unroll
        for (int i = tid; i < BM * BK / 4; i += THREADS) {
            int r = i >> 2;
            int c = (i & 3) << 2;
            float4 v = *(const float4*)(A + (size_t)(bm + r) * K + k0 + c);
            As[c + 0][r] = v.x; As[c + 1][r] = v.y; As[c + 2][r] = v.z; As[c + 3][r] = v.w;
        }
        #pragma unroll
        for (int i = tid; i < BN * BK / 4; i += THREADS) {
            int r = i >> 2;
            int c = (i & 3) << 2;
            float4 v = *(const float4*)(B + (size_t)(bn + r) * K + k0 + c);
            Bs[c + 0][r] = v.x; Bs[c + 1][r] = v.y; Bs[c + 2][r] = v.z; Bs[c + 3][r] = v.w;
        }
        __syncthreads();
        #pragma unroll
        for (int k = 0; k < BK; k++) {
            float4 a0 = *(const float4*)&As[k][trow * TM];
            float4 a1 = *(const float4*)&As[k][trow * TM + 4];
            float4 b0 = *(const float4*)&Bs[k][tcol * TN];
            float av[TM] = {a0.x, a0.y, a0.z, a0.w, a1.x, a1.y, a1.z, a1.w};
            float bv[TN] = {b0.x, b0.y, b0.z, b0.w};
            #pragma unroll
            for (int i = 0; i < TM; i++)
                #pragma unroll
                for (int j = 0; j < TN; j++) acc[i][j] += av[i] * bv[j];
        }
        __syncthreads();
    }
    int row0 = bm + trow * TM;
    int col0 = bn + tcol * TN;
    #pragma unroll
    for (int i = 0; i < TM; i++) {
        size_t base = (size_t)(row0 + i) * N + col0;
        #pragma unroll
        for (int j = 0; j < TN; j++) {
            float v = acc[i][j] + bias[col0 + j];
            if (RELU) v = v > 0.f ? v : 0.f;
            if (RES) v += res[base + j];
            C[base + j] = v;
        }
    }
}

// ===================== GAT edge kernels =====================
__global__ void degea_kernel(const int* __restrict__ edst, const float* __restrict__ ea,
                             float* __restrict__ eam, float* __restrict__ deg, int E) {
    int i = blockIdx.x * blockDim.x + threadIdx.x;
    if (i >= E * 8) return;
    int e = i >> 3, k4 = i & 7;
    int d = __ldg(edst + e);
    float4 v = *(const float4*)(ea + (size_t)e * DE + k4 * 4);
    float* p = eam + (size_t)d * DE + k4 * 4;
    asm volatile("red.global.add.v4.f32 [%0], {%1,%2,%3,%4};"
                 :: "l"(p), "f"(v.x), "f"(v.y), "f"(v.z), "f"(v.w) : "memory");
    if (k4 == 0) {
        float* q = deg + d;
        asm volatile("red.global.add.f32 [%0], %1;" :: "l"(q), "f"(1.0f) : "memory");
    }
}

__global__ void eamdiv_kernel(float* __restrict__ eam, const float* __restrict__ deg, int n32) {
    int i = blockIdx.x * blockDim.x + threadIdx.x;
    if (i >= n32) return;
    eam[i] *= 1.f / fmaxf(deg[i >> 5], 1.f);
}

__global__ void init_smax_kernel(unsigned* __restrict__ smax, int n) {
    int i = blockIdx.x * blockDim.x + threadIdx.x;
    if (i < n) smax[i] = 0x007FFFFFu;  // fenc(-inf)
}

// ===================== MMA-based score kernel =====================
#define SC_TE   16
#define SC_EFP  520
#define SC_SMEM ((512 * 36 + 512 + SC_TE * 36 + SC_TE * SC_EFP) * 4)
__global__ __launch_bounds__(256)
void score_mma_kernel(const float* __restrict__ XL, const float* __restrict__ XR,
                      const int* __restrict__ esrc, const int* __restrict__ edst,
                      const float* __restrict__ eattr, const float* __restrict__ eam,
                      const float* __restrict__ We, const float* __restrict__ att,
                      float* __restrict__ SC, unsigned* __restrict__ SMAX,
                      int E, int ET) {
    extern __shared__ float sm[];
    float* We_s = sm;
    float* att_s = We_s + 512 * 36;
    float* As   = att_s + 512;
    float* EF   = As + SC_TE * 36;
    __shared__ int src_s[SC_TE], dst_s[SC_TE];
    int tid = threadIdx.x;
    int wid = tid >> 5, lane = tid & 31;
    int lq = lane >> 2, lr = lane & 3;

    for (int i = tid; i < 512 * 8; i += 256) {
        int r = i >> 3, c = (i & 7) << 2;
        float4 v = *(const float4*)(We + (size_t)r * DE + c);
        float4 t = make_float4(tf32r(v.x), tf32r(v.y), tf32r(v.z), tf32r(v.w));
        *(float4*)&We_s[r * 36 + c] = t;
    }
    for (int i = tid; i < 512; i += 256) att_s[i] = att[i];
    __syncthreads();

    for (int base = blockIdx.x * SC_TE; base < ET; base += gridDim.x * SC_TE) {
        if (tid < SC_TE) {
            int e = base + tid;
            int s = 0, d = 0;
            if (e < ET) {
                if (e < E) { s = __ldg(esrc + e); d = __ldg(edst + e); }
                else       { s = d = e - E; }
            }
            src_s[tid] = s; dst_s[tid] = d;
        }
        for (int i = tid; i < SC_TE * DE; i += 256) {
            int el = i >> 5, k = i & 31;
            int e = base + el;
            float v = 0.f;
            if (e < ET) v = (e < E) ? __ldg(eattr + (size_t)e * DE + k)
                                    : __ldg(eam + (size_t)(e - E) * DE + k);
            As[el * 36 + k] = tf32r(v);
        }
        __syncthreads();

        {
            float c[8][4];
            #pragma unroll
            for (int nt = 0; nt < 8; nt++)
                #pragma unroll
                for (int r = 0; r < 4; r++) c[nt][r] = 0.f;
            #pragma unroll
            for (int kk = 0; kk < 32; kk += 8) {
                uint32_t a0 = __float_as_uint(As[lq * 36 + kk + lr]);
                uint32_t a1 = __float_as_uint(As[(lq + 8) * 36 + kk + lr]);
                uint32_t a2 = __float_as_uint(As[lq * 36 + kk + lr + 4]);
                uint32_t a3 = __float_as_uint(As[(lq + 8) * 36 + kk + lr + 4]);
                #pragma unroll
                for (int nt = 0; nt < 8; nt++) {
                    int col = wid * 64 + nt * 8 + lq;
                    uint32_t b0 = __float_as_uint(We_s[col * 36 + kk + lr]);
                    uint32_t b1 = __float_as_uint(We_s[col * 36 + kk + lr + 4]);
                    asm volatile(
                        "mma.sync.aligned.m16n8k8.row.col.f32.tf32.tf32.f32 "
                        "{%0,%1,%2,%3}, {%4,%5,%6,%7}, {%8,%9}, {%0,%1,%2,%3};"
                        : "+f"(c[nt][0]), "+f"(c[nt][1]), "+f"(c[nt][2]), "+f"(c[nt][3])
                        : "r"(a0), "r"(a1), "r"(a2), "r"(a3), "r"(b0), "r"(b1));
                }
            }
            #pragma unroll
            for (int nt = 0; nt < 8; nt++) {
                int col0 = wid * 64 + nt * 8 + lr * 2;
                EF[lq * SC_EFP + col0]           = c[nt][0];
                EF[lq * SC_EFP + col0 + 1]       = c[nt][1];
                EF[(lq + 8) * SC_EFP + col0]     = c[nt][2];
                EF[(lq + 8) * SC_EFP + col0 + 1] = c[nt][3];
            }
        }
        __syncthreads();

        #pragma unroll
        for (int sub = 0; sub < 2; sub++) {
            int el = wid * 2 + sub;
            int e = base + el;
            if (e >= ET) break;
            int s = src_s[el], d = dst_s[el];
            const float* xlp = XL + (size_t)s * HD;
            const float* xrp = XR + (size_t)d * HD;
            const float* efp = EF + el * SC_EFP;
            float ah[4] = {0.f, 0.f, 0.f, 0.f};
            #pragma unroll
            for (int j = 0; j < 16; j++) {
                int idx = lane + 32 * j;
                float v = __ldg(xlp + idx) + __ldg(xrp + idx) + efp[idx];
                v = v > 0.f ? v : SLOPE * v;
                ah[j >> 2] += v * att_s[idx];
            }
            #pragma unroll
            for (int h = 0; h < 4; h++) {
                float v = ah[h];
                #pragma unroll
                for (int o = 16; o > 0; o >>= 1) v += __shfl_down_sync(0xFFFFFFFFu, v, o);
                if (lane == 0) {
                    SC[(size_t)e * HEADS + h] = v;
                    atomicMax(&SMAX[(size_t)d * HEADS + h], fenc(v));
                }
            }
        }
        __syncthreads();
    }
}

__global__ void exp_kernel(float* __restrict__ SC, const unsigned* __restrict__ SMAX,
                           float* __restrict__ den, const int* __restrict__ edst,
                           int E, int ET) {
    int i = blockIdx.x * blockDim.x + threadIdx.x;
    if (i >= ET * HEADS) return;
    int e = i >> 2, h = i & 3;
    int d = (e < E) ? __ldg(edst + e) : (e - E);
    float m = fdec(SMAX[d * HEADS + h]);
    float ex = expf(SC[i] - m);
    SC[i] = ex;
    atomicAdd(&den[d * HEADS + h], ex);
}

__global__ void alpha_kernel(float* __restrict__ SC, const float* __restrict__ den,
                             const int* __restrict__ edst, float* __restrict__ out_alpha,
                             int E, int ET, int write_out) {
    int i = blockIdx.x * blockDim.x + threadIdx.x;
    if (i >= ET * HEADS) return;
    int e = i >> 2, h = i & 3;
    int d = (e < E) ? __ldg(edst + e) : (e - E);
    float a = SC[i] / den[d * HEADS + h];
    SC[i] = a;
    if (write_out) out_alpha[i] = a;
}

// one warp per edge, head-mixed: AGG[dst,c] += sum_h alpha_h * XL[src, h*128+c]
__global__ void aggregate_kernel(const float* __restrict__ XL, const float* __restrict__ SC,
                                 const int* __restrict__ esrc, const int* __restrict__ edst,
                                 float* __restrict__ AGG, int E, int ET) {
    int warp = (blockIdx.x * blockDim.x + threadIdx.x) >> 5;
    int lane = threadIdx.x & 31;
    if (warp >= ET) return;
    int e = warp;
    int s = (e < E) ? __ldg(esrc + e) : (e - E);
    int d = (e < E) ? __ldg(edst + e) : (e - E);
    float4 al = *(const float4*)(SC + (size_t)e * HEADS);
    const float4* xl4 = (const float4*)(XL + (size_t)s * HD);
    float4 v0 = __ldg(xl4 + 0 * 32 + lane);
    float4 v1 = __ldg(xl4 + 1 * 32 + lane);
    float4 v2 = __ldg(xl4 + 2 * 32 + lane);
    float4 v3 = __ldg(xl4 + 3 * 32 + lane);
    float rx = al.x * v0.x + al.y * v1.x + al.z * v2.x + al.w * v3.x;
    float ry = al.x * v0.y + al.y * v1.y + al.z * v2.y + al.w * v3.y;
    float rz = al.x * v0.z + al.y * v1.z + al.z * v2.z + al.w * v3.z;
    float rw = al.x * v0.w + al.y * v1.w + al.z * v2.w + al.w * v3.w;
    float* p = AGG + (size_t)d * DIM + lane * 4;
    asm volatile("red.global.add.v4.f32 [%0], {%1,%2,%3,%4};"
                 :: "l"(p), "f"(rx), "f"(ry), "f"(rz), "f"(rw) : "memory");
}

// fused: s1 = xn0 + 0.25*agg + gb  AND fp64 stats of s1 (grid-stride)
__global__ void headmean_stats_kernel(const float* __restrict__ xn0, const float* __restrict__ agg,
                                      const float* __restrict__ gb, float* __restrict__ s1,
                                      double* __restrict__ st, int total) {
    double s = 0.0, s2 = 0.0;
    for (int i = blockIdx.x * blockDim.x + threadIdx.x; i < total; i += gridDim.x * blockDim.x) {
        float v = xn0[i] + 0.25f * agg[i] + gb[i & 127];
        s1[i] = v;
        s += (double)v;
        s2 += (double)v * (double)v;
    }
    __shared__ double sh[256], sh2[256];
    int tid = threadIdx.x;
    sh[tid] = s; sh2[tid] = s2;
    __syncthreads();
    for (int o = 128; o > 0; o >>= 1) {
        if (tid < o) { sh[tid] += sh[tid + o]; sh2[tid] += sh2[tid + o]; }
        __syncthreads();
    }
    if (tid == 0) {
        atomicAdd(&st[0], sh[0]);
        atomicAdd(&st[1], sh2[0]);
    }
}

// ===================== launch =====================
extern "C" void kernel_launch(void* const* d_in, const int* in_sizes, int n_in,
                              void* d_out, int out_size) {
    const float* x   = (const float*)d_in[0];
    const int* ei    = (const int*)d_in[1];
    const float* ea  = (const float*)d_in[2];
    // d_in[3] = batch (unused, all zeros)
    const float* Wl  = (const float*)d_in[4];
    const float* bl  = (const float*)d_in[5];
    const float* Wr  = (const float*)d_in[6];
    const float* br  = (const float*)d_in[7];
    const float* We  = (const float*)d_in[8];
    const float* att = (const float*)d_in[9];
    const float* gb  = (const float*)d_in[10];
    const float* W1  = (const float*)d_in[11];
    const float* b1  = (const float*)d_in[12];
    const float* W2  = (const float*)d_in[13];
    const float* b2  = (const float*)d_in[14];
    const float* Wc  = (const float*)d_in[15];
    const float* bc  = (const float*)d_in[16];
    const float* nw0 = (const float*)d_in[17];
    const float* nb0 = (const float*)d_in[18];
    const float* nw1 = (const float*)d_in[19];
    const float* nb1 = (const float*)d_in[20];
    const float* nw2 = (const float*)d_in[21];
    const float* nb2 = (const float*)d_in[22];
    const float* nw3 = (const float*)d_in[23];
    const float* nb3 = (const float*)d_in[24];

    const int N = in_sizes[0] / DIM;
    const int E = in_sizes[1] / 2;
    const int ET = E + N;
    const int* esrc = ei;
    const int* edst = ei + E;

    float *p_xn0, *p_xl, *p_xr, *p_eam, *p_deg, *p_den, *p_sc, *p_agg;
    float *p_s1, *p_s2, *p_s3, *p_s4, *p_h1, *p_oc;
    unsigned* p_smax;
    double* p_st;
    cudaGetSymbolAddress((void**)&p_xn0, g_xn0);
    cudaGetSymbolAddress((void**)&p_xl, g_xl);
    cudaGetSymbolAddress((void**)&p_xr, g_xr);
    cudaGetSymbolAddress((void**)&p_eam, g_eam);
    cudaGetSymbolAddress((void**)&p_deg, g_deg);
    cudaGetSymbolAddress((void**)&p_smax, g_smax);
    cudaGetSymbolAddress((void**)&p_den, g_den);
    cudaGetSymbolAddress((void**)&p_sc, g_sc);
    cudaGetSymbolAddress((void**)&p_agg, g_agg);
    cudaGetSymbolAddress((void**)&p_s1, g_s1);
    cudaGetSymbolAddress((void**)&p_s2, g_s2);
    cudaGetSymbolAddress((void**)&p_s3, g_s3);
    cudaGetSymbolAddress((void**)&p_s4, g_s4);
    cudaGetSymbolAddress((void**)&p_h1, g_h1);
    cudaGetSymbolAddress((void**)&p_oc, g_oc);
    cudaGetSymbolAddress((void**)&p_st, g_stats);

    cudaFuncSetAttribute(score_mma_kernel, cudaFuncAttributeMaxDynamicSharedMemorySize, SC_SMEM);

    // zero scratch
    cudaMemsetAsync(p_st, 0, 8 * sizeof(double));
    cudaMemsetAsync(p_deg, 0, (size_t)N * sizeof(float));
    cudaMemsetAsync(p_eam, 0, (size_t)N * DE * sizeof(float));
    cudaMemsetAsync(p_den, 0, (size_t)N * HEADS * sizeof(float));
    cudaMemsetAsync(p_agg, 0, (size_t)N * DIM * sizeof(float));
    cudaMemsetAsync(p_s3, 0, (size_t)N * DIM * sizeof(float));   // split-K target
    init_smax_kernel<<<(N * HEADS + 255) / 256, 256>>>(p_smax, N * HEADS);

    // norm0
    stats_kernel<<<1024, 256>>>(x, p_st + 0, N * DIM);
    norm_apply_kernel<<<(N * DIM + 255) / 256, 256>>>(x, p_xn0, nw0, nb0, p_st + 0, N * DIM, DIM);

    // x_l / x_r  (TF32 tensor cores)
    {
        dim3 grid(HD / 128, N / 128);
        gemm_tf32_kernel<false, false><<<grid, 256>>>(p_xn0, Wl, bl, nullptr, p_xl, N, HD, DIM);
        gemm_tf32_kernel<false, false><<<grid, 256>>>(p_xn0, Wr, br, nullptr, p_xr, N, HD, DIM);
    }

    // self-loop edge attr (scatter-mean)
    degea_kernel<<<(E * 8 + 255) / 256, 256>>>(edst, ea, p_eam, p_deg, E);
    eamdiv_kernel<<<(N * DE + 255) / 256, 256>>>(p_eam, p_deg, N * DE);

    // scores + segment max  (MMA e_feat + warp-per-edge)
    score_mma_kernel<<<1024, 256, SC_SMEM>>>(
        p_xl, p_xr, esrc, edst, ea, p_eam, We, att, p_sc, p_smax, E, ET);

    // softmax
    exp_kernel<<<(ET * HEADS + 255) / 256, 256>>>(p_sc, p_smax, p_den, edst, E, ET);
    int write_alpha = (out_size >= N * DOUT + ET * HEADS) ? 1 : 0;
    alpha_kernel<<<(ET * HEADS + 255) / 256, 256>>>(
        p_sc, p_den, edst, (float*)d_out + (size_t)N * DOUT, E, ET, write_alpha);

    // aggregate (head-mixed, N x 128)
    aggregate_kernel<<<(ET * 32 + 255) / 256, 256>>>(p_xl, p_sc, esrc, edst, p_agg, E, ET);

    // residual + gat bias + head mean + stats (fused)
    headmean_stats_kernel<<<1024, 256>>>(p_xn0, p_agg, gb, p_s1, p_st + 2, N * DIM);

    // norm1
    norm_apply_kernel<<<(N * DIM + 255) / 256, 256>>>(p_s1, p_s2, nw1, nb1, p_st + 2, N * DIM, DIM);

    // MLP: relu(s2 @ W1^T + b1) @ W2^T + b2 + s2   (TF32; GEMM2 split-K)
    {
        dim3 g1(DHID / 128, N / 128);
        gemm_tf32_kernel<true, false><<<g1, 256>>>(p_s2, W1, b1, nullptr, p_h1, N, DHID, DIM);
        dim3 g2(DIM / 128, N / 128, 4);
        gemm_tf32_splitk_kernel<<<g2, 256>>>(p_h1, W2, b2, p_s2, p_s3, N, DIM, DHID, DHID / 4);
    }

    // norm2
    stats_kernel<<<1024, 256>>>(p_s3, p_st + 4, N * DIM);
    norm_apply_kernel<<<(N * DIM + 255) / 256, 256>>>(p_s3, p_s4, nw2, nb2, p_st + 4, N * DIM, DIM);

    // classifier (N=64 -> SIMT kernel)
    {
        dim3 g(DOUT / 64, N / 128);
        gemm_kernel<false, false><<<g, 256>>>(p_s4, Wc, bc, nullptr, p_oc, N, DOUT, DIM);
    }

    // norm3 -> output
    stats_kernel<<<1024, 256>>>(p_oc, p_st + 6, N * DOUT);
    norm_apply_kernel<<<(N * DOUT + 255) / 256, 256>>>(p_oc, (float*)d_out, nw3, nb3,
                                                       p_st + 6, N * DOUT, DOUT);
}

// round 12
// speedup vs baseline: 2.9396x; 1.0492x over previous
#include <cuda_runtime.h>
#include <cstdint>

// ===================== problem constants =====================
#define DIM    128      // D
#define HEADS  4        // H
#define DE     32       // edge feature dim
#define HD     512      // H*D
#define DHID   2048
#define DOUT   64
#define NMAX   16384
#define EMAX   131072
#define ETMAX  (EMAX + NMAX)
#define EPSN   1e-5f
#define SLOPE  0.2f

// ===================== scratch (static device globals; no allocs) ==========
__device__ float    g_xn0[NMAX * DIM];
__device__ float    g_xl[NMAX * HD];
__device__ float    g_xr[NMAX * HD];
__device__ float    g_eam[NMAX * DE];
__device__ float    g_deg[NMAX];
__device__ unsigned g_smax[NMAX * HEADS];
__device__ float    g_den[NMAX * HEADS];
__device__ float    g_sc[ETMAX * HEADS];
__device__ float    g_agg[NMAX * DIM];     // head-mixed: N x 128
__device__ float    g_s1[NMAX * DIM];
__device__ float    g_s2[NMAX * DIM];
__device__ float    g_s3[NMAX * DIM];
__device__ float    g_s4[NMAX * DIM];
__device__ float    g_h1[NMAX * DHID];
__device__ float    g_oc[NMAX * DOUT];
__device__ double   g_stats[8];

// ===================== helpers =====================
__device__ __forceinline__ unsigned fenc(float f) {
    unsigned u = __float_as_uint(f);
    return u ^ ((u >> 31) ? 0xFFFFFFFFu : 0x80000000u);
}
__device__ __forceinline__ float fdec(unsigned u) {
    unsigned v = u ^ ((u >> 31) ? 0x80000000u : 0xFFFFFFFFu);
    return __uint_as_float(v);
}
__device__ __forceinline__ float tf32r(float x) {
    uint32_t r;
    asm("cvt.rna.tf32.f32 %0, %1;" : "=r"(r) : "f"(x));
    return __uint_as_float(r);
}

// ===================== norm stats: sum & sumsq in fp64 =====================
__global__ void stats_kernel(const float* __restrict__ x, double* __restrict__ st, int n) {
    double s = 0.0, s2 = 0.0;
    for (int i = blockIdx.x * blockDim.x + threadIdx.x; i < n; i += gridDim.x * blockDim.x) {
        float v = x[i];
        s += (double)v;
        s2 += (double)v * (double)v;
    }
    __shared__ double sh[256], sh2[256];
    int tid = threadIdx.x;
    sh[tid] = s; sh2[tid] = s2;
    __syncthreads();
    for (int o = 128; o > 0; o >>= 1) {
        if (tid < o) { sh[tid] += sh[tid + o]; sh2[tid] += sh2[tid + o]; }
        __syncthreads();
    }
    if (tid == 0) {
        atomicAdd(&st[0], sh[0]);
        atomicAdd(&st[1], sh2[0]);
    }
}

__global__ void norm_apply_kernel(const float* __restrict__ x, float* __restrict__ y,
                                  const float* __restrict__ w, const float* __restrict__ b,
                                  const double* __restrict__ st, int n, int C) {
    int i = blockIdx.x * blockDim.x + threadIdx.x;
    if (i >= n) return;
    double cnt = (double)n;
    double mu_d = st[0] / cnt;
    double var_d = st[1] / cnt - mu_d * mu_d;
    if (var_d < 0.0) var_d = 0.0;
    float mu = (float)mu_d;
    float inv = 1.0f / ((float)sqrt(var_d) + EPSN);
    int c = i % C;
    y[i] = (x[i] - mu) * inv * w[c] + b[c];
}

// ===================== pipelined TF32 GEMM: C = A[M,K]*B[N,K]^T (+bias) =====
// 2-stage cp.async pipeline. If SPLITK: C pre-zeroed, partials via red.global,
// z==0 adds bias+res. Else: direct store with bias (+relu) (+res).
template <bool RELU, bool RES, bool SPLITK>
__global__ __launch_bounds__(256, 2)
void gemm_tf32_pipe_kernel(const float* __restrict__ A, const float* __restrict__ B,
                           const float* __restrict__ bias, const float* __restrict__ res,
                           float* __restrict__ C, int M, int N, int K, int Kc) {
    constexpr int BM = 128, BN = 128, BK = 32, LDS_ = 36;
    constexpr int STAGE = (BM + BN) * LDS_;   // floats per stage
    extern __shared__ float smem[];
    int tid = threadIdx.x;
    int wid = tid >> 5, lane = tid & 31;
    int warp_m = wid & 1;
    int warp_n = wid >> 1;
    int bm = blockIdx.y * BM, bn = blockIdx.x * BN;
    int kz0 = SPLITK ? blockIdx.z * Kc : 0;
    int kz1 = SPLITK ? ((kz0 + Kc < K) ? kz0 + Kc : K) : K;
    int lq = lane >> 2;
    int lr = lane & 3;

    float acc[4][4][4];
    #pragma unroll
    for (int mi = 0; mi < 4; mi++)
        #pragma unroll
        for (int ni = 0; ni < 4; ni++)
            #pragma unroll
            for (int r = 0; r < 4; r++) acc[mi][ni][r] = 0.f;

    // per-thread load coords (same for every stage)
    int l_r[4], l_c[4];
    #pragma unroll
    for (int it = 0; it < 4; it++) {
        int idx = it * 256 + tid;
        l_r[it] = idx >> 3;
        l_c[it] = (idx & 7) << 2;
    }

    auto load_stage = [&](int k0, int st) {
        float* As = smem + st * STAGE;
        float* Bs = As + BM * LDS_;
        #pragma unroll
        for (int it = 0; it < 4; it++) {
            uint32_t sa = (uint32_t)__cvta_generic_to_shared(&As[l_r[it] * LDS_ + l_c[it]]);
            const float* g = A + (size_t)(bm + l_r[it]) * K + k0 + l_c[it];
            asm volatile("cp.async.cg.shared.global [%0], [%1], 16;" :: "r"(sa), "l"(g));
        }
        #pragma unroll
        for (int it = 0; it < 4; it++) {
            uint32_t sb = (uint32_t)__cvta_generic_to_shared(&Bs[l_r[it] * LDS_ + l_c[it]]);
            const float* g = B + (size_t)(bn + l_r[it]) * K + k0 + l_c[it];
            asm volatile("cp.async.cg.shared.global [%0], [%1], 16;" :: "r"(sb), "l"(g));
        }
        asm volatile("cp.async.commit_group;");
    };

    int niter = (kz1 - kz0) / BK;
    load_stage(kz0, 0);
    for (int i = 0; i < niter; i++) {
        int cur = i & 1;
        if (i + 1 < niter) {
            load_stage(kz0 + (i + 1) * BK, cur ^ 1);
            asm volatile("cp.async.wait_group 1;");
        } else {
            asm volatile("cp.async.wait_group 0;");
        }
        __syncthreads();
        float* As = smem + cur * STAGE;
        float* Bs = As + BM * LDS_;

        #pragma unroll
        for (int kk = 0; kk < BK; kk += 8) {
            uint32_t a[4][4], b[4][2];
            #pragma unroll
            for (int mi = 0; mi < 4; mi++) {
                int row = warp_m * 64 + mi * 16 + lq;
                a[mi][0] = __float_as_uint(As[row * LDS_ + kk + lr]);
                a[mi][1] = __float_as_uint(As[(row + 8) * LDS_ + kk + lr]);
                a[mi][2] = __float_as_uint(As[row * LDS_ + kk + lr + 4]);
                a[mi][3] = __float_as_uint(As[(row + 8) * LDS_ + kk + lr + 4]);
            }
            #pragma unroll
            for (int ni = 0; ni < 4; ni++) {
                int col = warp_n * 32 + ni * 8 + lq;
                b[ni][0] = __float_as_uint(Bs[col * LDS_ + kk + lr]);
                b[ni][1] = __float_as_uint(Bs[col * LDS_ + kk + lr + 4]);
            }
            #pragma unroll
            for (int mi = 0; mi < 4; mi++)
                #pragma unroll
                for (int ni = 0; ni < 4; ni++) {
                    asm volatile(
                        "mma.sync.aligned.m16n8k8.row.col.f32.tf32.tf32.f32 "
                        "{%0,%1,%2,%3}, {%4,%5,%6,%7}, {%8,%9}, {%0,%1,%2,%3};"
                        : "+f"(acc[mi][ni][0]), "+f"(acc[mi][ni][1]),
                          "+f"(acc[mi][ni][2]), "+f"(acc[mi][ni][3])
                        : "r"(a[mi][0]), "r"(a[mi][1]), "r"(a[mi][2]), "r"(a[mi][3]),
                          "r"(b[ni][0]), "r"(b[ni][1]));
                }
        }
        __syncthreads();
    }

    if (SPLITK) {
        bool first = (blockIdx.z == 0);
        #pragma unroll
        for (int mi = 0; mi < 4; mi++) {
            int row = bm + warp_m * 64 + mi * 16 + lq;
            #pragma unroll
            for (int ni = 0; ni < 4; ni++) {
                int col = bn + warp_n * 32 + ni * 8 + (lr << 1);
                #pragma unroll
                for (int h = 0; h < 2; h++) {
                    int rr = row + h * 8;
                    float v0 = acc[mi][ni][h * 2 + 0];
                    float v1 = acc[mi][ni][h * 2 + 1];
                    size_t o = (size_t)rr * N + col;
                    if (first) {
                        v0 += bias[col] + res[o];
                        v1 += bias[col + 1] + res[o + 1];
                    }
                    asm volatile("red.global.add.v2.f32 [%0], {%1,%2};"
                                 :: "l"(C + o), "f"(v0), "f"(v1) : "memory");
                }
            }
        }
    } else {
        #pragma unroll
        for (int mi = 0; mi < 4; mi++) {
            int row = bm + warp_m * 64 + mi * 16 + lq;
            #pragma unroll
            for (int ni = 0; ni < 4; ni++) {
                int col = bn + warp_n * 32 + ni * 8 + (lr << 1);
                float b0 = bias[col], b1 = bias[col + 1];
                #pragma unroll
                for (int h = 0; h < 2; h++) {
                    int rr = row + h * 8;
                    float v0 = acc[mi][ni][h * 2 + 0] + b0;
                    float v1 = acc[mi][ni][h * 2 + 1] + b1;
                    if (RELU) { v0 = fmaxf(v0, 0.f); v1 = fmaxf(v1, 0.f); }
                    size_t o = (size_t)rr * N + col;
                    if (RES) { v0 += res[o]; v1 += res[o + 1]; }
                    *(float2*)(C + o) = make_float2(v0, v1);
                }
            }
        }
    }
}

#define GEMM_PIPE_SMEM (2 * (128 + 128) * 36 * 4)

// ===================== SIMT SGEMM (small N: classifier) =====================
template <bool RELU, bool RES>
__global__ void gemm_kernel(const float* __restrict__ A, const float* __restrict__ B,
                            const float* __restrict__ bias, const float* __restrict__ res,
                            float* __restrict__ C, int M, int N, int K) {
    constexpr int BM = 128, BN = 64, BK = 16, TM = 8, TN = 4, THREADS = 256;
    __shared__ float As[BK][BM];
    __shared__ float Bs[BK][BN];
    int tid = threadIdx.x;
    int bm = blockIdx.y * BM, bn = blockIdx.x * BN;
    int tcol = tid & 15;
    int trow = tid >> 4;
    float acc[TM][TN];
    #pragma unroll
    for (int i = 0; i < TM; i++)
        #pragma unroll
        for (int j = 0; j < TN; j++) acc[i][j] = 0.f;

    for (int k0 = 0; k0 < K; k0 += BK) {
        #pragma unroll
        for (int i = tid; i < BM * BK / 4; i += THREADS) {
            int r = i >> 2;
            int c = (i & 3) << 2;
            float4 v = *(const float4*)(A + (size_t)(bm + r) * K + k0 + c);
            As[c + 0][r] = v.x; As[c + 1][r] = v.y; As[c + 2][r] = v.z; As[c + 3][r] = v.w;
        }
        #pragma unroll
        for (int i = tid; i < BN * BK / 4; i += THREADS) {
            int r = i >> 2;
            int c = (i & 3) << 2;
            float4 v = *(const float4*)(B + (size_t)(bn + r) * K + k0 + c);
            Bs[c + 0][r] = v.x; Bs[c + 1][r] = v.y; Bs[c + 2][r] = v.z; Bs[c + 3][r] = v.w;
        }
        __syncthreads();
        #pragma unroll
        for (int k = 0; k < BK; k++) {
            float4 a0 = *(const float4*)&As[k][trow * TM];
            float4 a1 = *(const float4*)&As[k][trow * TM + 4];
            float4 b0 = *(const float4*)&Bs[k][tcol * TN];
            float av[TM] = {a0.x, a0.y, a0.z, a0.w, a1.x, a1.y, a1.z, a1.w};
            float bv[TN] = {b0.x, b0.y, b0.z, b0.w};
            #pragma unroll
            for (int i = 0; i < TM; i++)
                #pragma unroll
                for (int j = 0; j < TN; j++) acc[i][j] += av[i] * bv[j];
        }
        __syncthreads();
    }
    int row0 = bm + trow * TM;
    int col0 = bn + tcol * TN;
    #pragma unroll
    for (int i = 0; i < TM; i++) {
        size_t base = (size_t)(row0 + i) * N + col0;
        #pragma unroll
        for (int j = 0; j < TN; j++) {
            float v = acc[i][j] + bias[col0 + j];
            if (RELU) v = v > 0.f ? v : 0.f;
            if (RES) v += res[base + j];
            C[base + j] = v;
        }
    }
}

// ===================== GAT edge kernels =====================
__global__ void degea_kernel(const int* __restrict__ edst, const float* __restrict__ ea,
                             float* __restrict__ eam, float* __restrict__ deg, int E) {
    int i = blockIdx.x * blockDim.x + threadIdx.x;
    if (i >= E * 8) return;
    int e = i >> 3, k4 = i & 7;
    int d = __ldg(edst + e);
    float4 v = *(const float4*)(ea + (size_t)e * DE + k4 * 4);
    float* p = eam + (size_t)d * DE + k4 * 4;
    asm volatile("red.global.add.v4.f32 [%0], {%1,%2,%3,%4};"
                 :: "l"(p), "f"(v.x), "f"(v.y), "f"(v.z), "f"(v.w) : "memory");
    if (k4 == 0) {
        float* q = deg + d;
        asm volatile("red.global.add.f32 [%0], %1;" :: "l"(q), "f"(1.0f) : "memory");
    }
}

__global__ void eamdiv_kernel(float* __restrict__ eam, const float* __restrict__ deg, int n32) {
    int i = blockIdx.x * blockDim.x + threadIdx.x;
    if (i >= n32) return;
    eam[i] *= 1.f / fmaxf(deg[i >> 5], 1.f);
}

__global__ void init_smax_kernel(unsigned* __restrict__ smax, int n) {
    int i = blockIdx.x * blockDim.x + threadIdx.x;
    if (i < n) smax[i] = 0x007FFFFFu;  // fenc(-inf)
}

// ===================== MMA-based score kernel =====================
#define SC_TE   16
#define SC_EFP  520
#define SC_SMEM ((512 * 36 + 512 + SC_TE * 36 + SC_TE * SC_EFP) * 4)
__global__ __launch_bounds__(256)
void score_mma_kernel(const float* __restrict__ XL, const float* __restrict__ XR,
                      const int* __restrict__ esrc, const int* __restrict__ edst,
                      const float* __restrict__ eattr, const float* __restrict__ eam,
                      const float* __restrict__ We, const float* __restrict__ att,
                      float* __restrict__ SC, unsigned* __restrict__ SMAX,
                      int E, int ET) {
    extern __shared__ float sm[];
    float* We_s = sm;
    float* att_s = We_s + 512 * 36;
    float* As   = att_s + 512;
    float* EF   = As + SC_TE * 36;
    __shared__ int src_s[SC_TE], dst_s[SC_TE];
    int tid = threadIdx.x;
    int wid = tid >> 5, lane = tid & 31;
    int lq = lane >> 2, lr = lane & 3;

    for (int i = tid; i < 512 * 8; i += 256) {
        int r = i >> 3, c = (i & 7) << 2;
        float4 v = *(const float4*)(We + (size_t)r * DE + c);
        float4 t = make_float4(tf32r(v.x), tf32r(v.y), tf32r(v.z), tf32r(v.w));
        *(float4*)&We_s[r * 36 + c] = t;
    }
    for (int i = tid; i < 512; i += 256) att_s[i] = att[i];
    __syncthreads();

    for (int base = blockIdx.x * SC_TE; base < ET; base += gridDim.x * SC_TE) {
        if (tid < SC_TE) {
            int e = base + tid;
            int s = 0, d = 0;
            if (e < ET) {
                if (e < E) { s = __ldg(esrc + e); d = __ldg(edst + e); }
                else       { s = d = e - E; }
            }
            src_s[tid] = s; dst_s[tid] = d;
        }
        for (int i = tid; i < SC_TE * DE; i += 256) {
            int el = i >> 5, k = i & 31;
            int e = base + el;
            float v = 0.f;
            if (e < ET) v = (e < E) ? __ldg(eattr + (size_t)e * DE + k)
                                    : __ldg(eam + (size_t)(e - E) * DE + k);
            As[el * 36 + k] = tf32r(v);
        }
        __syncthreads();

        {
            float c[8][4];
            #pragma unroll
            for (int nt = 0; nt < 8; nt++)
                #pragma unroll
                for (int r = 0; r < 4; r++) c[nt][r] = 0.f;
            #pragma unroll
            for (int kk = 0; kk < 32; kk += 8) {
                uint32_t a0 = __float_as_uint(As[lq * 36 + kk + lr]);
                uint32_t a1 = __float_as_uint(As[(lq + 8) * 36 + kk + lr]);
                uint32_t a2 = __float_as_uint(As[lq * 36 + kk + lr + 4]);
                uint32_t a3 = __float_as_uint(As[(lq + 8) * 36 + kk + lr + 4]);
                #pragma unroll
                for (int nt = 0; nt < 8; nt++) {
                    int col = wid * 64 + nt * 8 + lq;
                    uint32_t b0 = __float_as_uint(We_s[col * 36 + kk + lr]);
                    uint32_t b1 = __float_as_uint(We_s[col * 36 + kk + lr + 4]);
                    asm volatile(
                        "mma.sync.aligned.m16n8k8.row.col.f32.tf32.tf32.f32 "
                        "{%0,%1,%2,%3}, {%4,%5,%6,%7}, {%8,%9}, {%0,%1,%2,%3};"
                        : "+f"(c[nt][0]), "+f"(c[nt][1]), "+f"(c[nt][2]), "+f"(c[nt][3])
                        : "r"(a0), "r"(a1), "r"(a2), "r"(a3), "r"(b0), "r"(b1));
                }
            }
            #pragma unroll
            for (int nt = 0; nt < 8; nt++) {
                int col0 = wid * 64 + nt * 8 + lr * 2;
                EF[lq * SC_EFP + col0]           = c[nt][0];
                EF[lq * SC_EFP + col0 + 1]       = c[nt][1];
                EF[(lq + 8) * SC_EFP + col0]     = c[nt][2];
                EF[(lq + 8) * SC_EFP + col0 + 1] = c[nt][3];
            }
        }
        __syncthreads();

        #pragma unroll
        for (int sub = 0; sub < 2; sub++) {
            int el = wid * 2 + sub;
            int e = base + el;
            if (e >= ET) break;
            int s = src_s[el], d = dst_s[el];
            const float* xlp = XL + (size_t)s * HD;
            const float* xrp = XR + (size_t)d * HD;
            const float* efp = EF + el * SC_EFP;
            float ah[4] = {0.f, 0.f, 0.f, 0.f};
            #pragma unroll
            for (int j = 0; j < 16; j++) {
                int idx = lane + 32 * j;
                float v = __ldg(xlp + idx) + __ldg(xrp + idx) + efp[idx];
                v = v > 0.f ? v : SLOPE * v;
                ah[j >> 2] += v * att_s[idx];
            }
            #pragma unroll
            for (int h = 0; h < 4; h++) {
                float v = ah[h];
                #pragma unroll
                for (int o = 16; o > 0; o >>= 1) v += __shfl_down_sync(0xFFFFFFFFu, v, o);
                if (lane == 0) {
                    SC[(size_t)e * HEADS + h] = v;
                    atomicMax(&SMAX[(size_t)d * HEADS + h], fenc(v));
                }
            }
        }
        __syncthreads();
    }
}

__global__ void exp_kernel(float* __restrict__ SC, const unsigned* __restrict__ SMAX,
                           float* __restrict__ den, const int* __restrict__ edst,
                           int E, int ET) {
    int i = blockIdx.x * blockDim.x + threadIdx.x;
    if (i >= ET * HEADS) return;
    int e = i >> 2, h = i & 3;
    int d = (e < E) ? __ldg(edst + e) : (e - E);
    float m = fdec(SMAX[d * HEADS + h]);
    float ex = expf(SC[i] - m);
    SC[i] = ex;
    atomicAdd(&den[d * HEADS + h], ex);
}

__global__ void alpha_kernel(float* __restrict__ SC, const float* __restrict__ den,
                             const int* __restrict__ edst, float* __restrict__ out_alpha,
                             int E, int ET, int write_out) {
    int i = blockIdx.x * blockDim.x + threadIdx.x;
    if (i >= ET * HEADS) return;
    int e = i >> 2, h = i & 3;
    int d = (e < E) ? __ldg(edst + e) : (e - E);
    float a = SC[i] / den[d * HEADS + h];
    SC[i] = a;
    if (write_out) out_alpha[i] = a;
}

// one warp per edge, head-mixed: AGG[dst,c] += sum_h alpha_h * XL[src, h*128+c]
__global__ void aggregate_kernel(const float* __restrict__ XL, const float* __restrict__ SC,
                                 const int* __restrict__ esrc, const int* __restrict__ edst,
                                 float* __restrict__ AGG, int E, int ET) {
    int warp = (blockIdx.x * blockDim.x + threadIdx.x) >> 5;
    int lane = threadIdx.x & 31;
    if (warp >= ET) return;
    int e = warp;
    int s = (e < E) ? __ldg(esrc + e) : (e - E);
    int d = (e < E) ? __ldg(edst + e) : (e - E);
    float4 al = *(const float4*)(SC + (size_t)e * HEADS);
    const float4* xl4 = (const float4*)(XL + (size_t)s * HD);
    float4 v0 = __ldg(xl4 + 0 * 32 + lane);
    float4 v1 = __ldg(xl4 + 1 * 32 + lane);
    float4 v2 = __ldg(xl4 + 2 * 32 + lane);
    float4 v3 = __ldg(xl4 + 3 * 32 + lane);
    float rx = al.x * v0.x + al.y * v1.x + al.z * v2.x + al.w * v3.x;
    float ry = al.x * v0.y + al.y * v1.y + al.z * v2.y + al.w * v3.y;
    float rz = al.x * v0.z + al.y * v1.z + al.z * v2.z + al.w * v3.z;
    float rw = al.x * v0.w + al.y * v1.w + al.z * v2.w + al.w * v3.w;
    float* p = AGG + (size_t)d * DIM + lane * 4;
    asm volatile("red.global.add.v4.f32 [%0], {%1,%2,%3,%4};"
                 :: "l"(p), "f"(rx), "f"(ry), "f"(rz), "f"(rw) : "memory");
}

// fused: s1 = xn0 + 0.25*agg + gb  AND fp64 stats of s1 (grid-stride)
__global__ void headmean_stats_kernel(const float* __restrict__ xn0, const float* __restrict__ agg,
                                      const float* __restrict__ gb, float* __restrict__ s1,
                                      double* __restrict__ st, int total) {
    double s = 0.0, s2 = 0.0;
    for (int i = blockIdx.x * blockDim.x + threadIdx.x; i < total; i += gridDim.x * blockDim.x) {
        float v = xn0[i] + 0.25f * agg[i] + gb[i & 127];
        s1[i] = v;
        s += (double)v;
        s2 += (double)v * (double)v;
    }
    __shared__ double sh[256], sh2[256];
    int tid = threadIdx.x;
    sh[tid] = s; sh2[tid] = s2;
    __syncthreads();
    for (int o = 128; o > 0; o >>= 1) {
        if (tid < o) { sh[tid] += sh[tid + o]; sh2[tid] += sh2[tid + o]; }
        __syncthreads();
    }
    if (tid == 0) {
        atomicAdd(&st[0], sh[0]);
        atomicAdd(&st[1], sh2[0]);
    }
}

// ===================== launch =====================
extern "C" void kernel_launch(void* const* d_in, const int* in_sizes, int n_in,
                              void* d_out, int out_size) {
    const float* x   = (const float*)d_in[0];
    const int* ei    = (const int*)d_in[1];
    const float* ea  = (const float*)d_in[2];
    // d_in[3] = batch (unused, all zeros)
    const float* Wl  = (const float*)d_in[4];
    const float* bl  = (const float*)d_in[5];
    const float* Wr  = (const float*)d_in[6];
    const float* br  = (const float*)d_in[7];
    const float* We  = (const float*)d_in[8];
    const float* att = (const float*)d_in[9];
    const float* gb  = (const float*)d_in[10];
    const float* W1  = (const float*)d_in[11];
    const float* b1  = (const float*)d_in[12];
    const float* W2  = (const float*)d_in[13];
    const float* b2  = (const float*)d_in[14];
    const float* Wc  = (const float*)d_in[15];
    const float* bc  = (const float*)d_in[16];
    const float* nw0 = (const float*)d_in[17];
    const float* nb0 = (const float*)d_in[18];
    const float* nw1 = (const float*)d_in[19];
    const float* nb1 = (const float*)d_in[20];
    const float* nw2 = (const float*)d_in[21];
    const float* nb2 = (const float*)d_in[22];
    const float* nw3 = (const float*)d_in[23];
    const float* nb3 = (const float*)d_in[24];

    const int N = in_sizes[0] / DIM;
    const int E = in_sizes[1] / 2;
    const int ET = E + N;
    const int* esrc = ei;
    const int* edst = ei + E;

    float *p_xn0, *p_xl, *p_xr, *p_eam, *p_deg, *p_den, *p_sc, *p_agg;
    float *p_s1, *p_s2, *p_s3, *p_s4, *p_h1, *p_oc;
    unsigned* p_smax;
    double* p_st;
    cudaGetSymbolAddress((void**)&p_xn0, g_xn0);
    cudaGetSymbolAddress((void**)&p_xl, g_xl);
    cudaGetSymbolAddress((void**)&p_xr, g_xr);
    cudaGetSymbolAddress((void**)&p_eam, g_eam);
    cudaGetSymbolAddress((void**)&p_deg, g_deg);
    cudaGetSymbolAddress((void**)&p_smax, g_smax);
    cudaGetSymbolAddress((void**)&p_den, g_den);
    cudaGetSymbolAddress((void**)&p_sc, g_sc);
    cudaGetSymbolAddress((void**)&p_agg, g_agg);
    cudaGetSymbolAddress((void**)&p_s1, g_s1);
    cudaGetSymbolAddress((void**)&p_s2, g_s2);
    cudaGetSymbolAddress((void**)&p_s3, g_s3);
    cudaGetSymbolAddress((void**)&p_s4, g_s4);
    cudaGetSymbolAddress((void**)&p_h1, g_h1);
    cudaGetSymbolAddress((void**)&p_oc, g_oc);
    cudaGetSymbolAddress((void**)&p_st, g_stats);

    cudaFuncSetAttribute(score_mma_kernel, cudaFuncAttributeMaxDynamicSharedMemorySize, SC_SMEM);
    cudaFuncSetAttribute(gemm_tf32_pipe_kernel<false, false, false>,
                         cudaFuncAttributeMaxDynamicSharedMemorySize, GEMM_PIPE_SMEM);
    cudaFuncSetAttribute(gemm_tf32_pipe_kernel<true, false, false>,
                         cudaFuncAttributeMaxDynamicSharedMemorySize, GEMM_PIPE_SMEM);
    cudaFuncSetAttribute(gemm_tf32_pipe_kernel<false, true, true>,
                         cudaFuncAttributeMaxDynamicSharedMemorySize, GEMM_PIPE_SMEM);

    // zero scratch
    cudaMemsetAsync(p_st, 0, 8 * sizeof(double));
    cudaMemsetAsync(p_deg, 0, (size_t)N * sizeof(float));
    cudaMemsetAsync(p_eam, 0, (size_t)N * DE * sizeof(float));
    cudaMemsetAsync(p_den, 0, (size_t)N * HEADS * sizeof(float));
    cudaMemsetAsync(p_agg, 0, (size_t)N * DIM * sizeof(float));
    cudaMemsetAsync(p_s3, 0, (size_t)N * DIM * sizeof(float));   // split-K target
    init_smax_kernel<<<(N * HEADS + 255) / 256, 256>>>(p_smax, N * HEADS);

    // norm0
    stats_kernel<<<1024, 256>>>(x, p_st + 0, N * DIM);
    norm_apply_kernel<<<(N * DIM + 255) / 256, 256>>>(x, p_xn0, nw0, nb0, p_st + 0, N * DIM, DIM);

    // x_l / x_r  (pipelined TF32)
    {
        dim3 grid(HD / 128, N / 128);
        gemm_tf32_pipe_kernel<false, false, false><<<grid, 256, GEMM_PIPE_SMEM>>>(
            p_xn0, Wl, bl, nullptr, p_xl, N, HD, DIM, 0);
        gemm_tf32_pipe_kernel<false, false, false><<<grid, 256, GEMM_PIPE_SMEM>>>(
            p_xn0, Wr, br, nullptr, p_xr, N, HD, DIM, 0);
    }

    // self-loop edge attr (scatter-mean)
    degea_kernel<<<(E * 8 + 255) / 256, 256>>>(edst, ea, p_eam, p_deg, E);
    eamdiv_kernel<<<(N * DE + 255) / 256, 256>>>(p_eam, p_deg, N * DE);

    // scores + segment max  (MMA e_feat + warp-per-edge)
    score_mma_kernel<<<1024, 256, SC_SMEM>>>(
        p_xl, p_xr, esrc, edst, ea, p_eam, We, att, p_sc, p_smax, E, ET);

    // softmax
    exp_kernel<<<(ET * HEADS + 255) / 256, 256>>>(p_sc, p_smax, p_den, edst, E, ET);
    int write_alpha = (out_size >= N * DOUT + ET * HEADS) ? 1 : 0;
    alpha_kernel<<<(ET * HEADS + 255) / 256, 256>>>(
        p_sc, p_den, edst, (float*)d_out + (size_t)N * DOUT, E, ET, write_alpha);

    // aggregate (head-mixed, N x 128)
    aggregate_kernel<<<(ET * 32 + 255) / 256, 256>>>(p_xl, p_sc, esrc, edst, p_agg, E, ET);

    // residual + gat bias + head mean + stats (fused)
    headmean_stats_kernel<<<1024, 256>>>(p_xn0, p_agg, gb, p_s1, p_st + 2, N * DIM);

    // norm1
    norm_apply_kernel<<<(N * DIM + 255) / 256, 256>>>(p_s1, p_s2, nw1, nb1, p_st + 2, N * DIM, DIM);

    // MLP: relu(s2 @ W1^T + b1) @ W2^T + b2 + s2   (pipelined; GEMM2 split-K)
    {
        dim3 g1(DHID / 128, N / 128);
        gemm_tf32_pipe_kernel<true, false, false><<<g1, 256, GEMM_PIPE_SMEM>>>(
            p_s2, W1, b1, nullptr, p_h1, N, DHID, DIM, 0);
        dim3 g2(DIM / 128, N / 128, 4);
        gemm_tf32_pipe_kernel<false, true, true><<<g2, 256, GEMM_PIPE_SMEM>>>(
            p_h1, W2, b2, p_s2, p_s3, N, DIM, DHID, DHID / 4);
    }

    // norm2
    stats_kernel<<<1024, 256>>>(p_s3, p_st + 4, N * DIM);
    norm_apply_kernel<<<(N * DIM + 255) / 256, 256>>>(p_s3, p_s4, nw2, nb2, p_st + 4, N * DIM, DIM);

    // classifier (N=64 -> SIMT kernel)
    {
        dim3 g(DOUT / 64, N / 128);
        gemm_kernel<false, false><<<g, 256>>>(p_s4, Wc, bc, nullptr, p_oc, N, DOUT, DIM);
    }

    // norm3 -> output
    stats_kernel<<<1024, 256>>>(p_oc, p_st + 6, N * DOUT);
    norm_apply_kernel<<<(N * DOUT + 255) / 256, 256>>>(p_oc, (float*)d_out, nw3, nb3,
                                                       p_st + 6, N * DOUT, DOUT);
}